// round 1
// baseline (speedup 1.0000x reference)
#include <cuda_runtime.h>
#include <math.h>

#define NB   2
#define TT   2048
#define DD   1024
#define HH   16
#define HDD  64
#define WL   127
#define WR   128

// Scratch (allocation-free): qkv = [N,T,3,D] fp32, attn = [N,T,D] fp32
__device__ float g_qkv[(size_t)NB * TT * 3 * DD];   // ~50 MB
__device__ float g_attn[(size_t)NB * TT * DD];      // ~17 MB

// ---------------------------------------------------------------------------
// SGEMM: C[m,n] = sum_k A[m,k] * B[n,k] (+ bias[n]).  A:[M,K], B:[N,K] row-major.
// 128x128x8 tiles, 8x8 per-thread, double-buffered smem, 256 threads.
// M,N multiples of 128; K multiple of 8 (true for all our shapes).
// ---------------------------------------------------------------------------
__global__ __launch_bounds__(256) void sgemm_nt(
    const float* __restrict__ A, const float* __restrict__ B,
    const float* __restrict__ bias, float* __restrict__ C,
    int M, int N, int K)
{
    const int BM = 128, BN = 128, BK = 8;
    __shared__ float As[2][BK][BM];
    __shared__ float Bs[2][BK][BN];

    const int tid  = threadIdx.x;
    const int m0   = blockIdx.y * BM;
    const int n0   = blockIdx.x * BN;
    const int lrow = tid >> 1;          // 0..127
    const int k4   = (tid & 1) * 4;     // 0 or 4
    const int ty   = tid >> 4;          // 0..15
    const int tx   = tid & 15;          // 0..15

    const float* Aptr = A + (size_t)(m0 + lrow) * K + k4;
    const float* Bptr = B + (size_t)(n0 + lrow) * K + k4;

    float4 aReg = *(const float4*)Aptr;
    float4 bReg = *(const float4*)Bptr;
    As[0][k4 + 0][lrow] = aReg.x; As[0][k4 + 1][lrow] = aReg.y;
    As[0][k4 + 2][lrow] = aReg.z; As[0][k4 + 3][lrow] = aReg.w;
    Bs[0][k4 + 0][lrow] = bReg.x; Bs[0][k4 + 1][lrow] = bReg.y;
    Bs[0][k4 + 2][lrow] = bReg.z; Bs[0][k4 + 3][lrow] = bReg.w;
    __syncthreads();

    float acc[8][8];
    #pragma unroll
    for (int r = 0; r < 8; r++)
        #pragma unroll
        for (int c = 0; c < 8; c++) acc[r][c] = 0.0f;

    const int kIters = K / BK;
    int buf = 0;
    for (int kt = 0; kt < kIters; kt++) {
        if (kt + 1 < kIters) {
            aReg = *(const float4*)(Aptr + (size_t)(kt + 1) * BK);
            bReg = *(const float4*)(Bptr + (size_t)(kt + 1) * BK);
        }
        #pragma unroll
        for (int k = 0; k < BK; k++) {
            float4 a0 = *(const float4*)&As[buf][k][ty * 8];
            float4 a1 = *(const float4*)&As[buf][k][ty * 8 + 4];
            float4 b0 = *(const float4*)&Bs[buf][k][tx * 8];
            float4 b1 = *(const float4*)&Bs[buf][k][tx * 8 + 4];
            float av[8] = {a0.x, a0.y, a0.z, a0.w, a1.x, a1.y, a1.z, a1.w};
            float bv[8] = {b0.x, b0.y, b0.z, b0.w, b1.x, b1.y, b1.z, b1.w};
            #pragma unroll
            for (int r = 0; r < 8; r++)
                #pragma unroll
                for (int c = 0; c < 8; c++)
                    acc[r][c] = fmaf(av[r], bv[c], acc[r][c]);
        }
        if (kt + 1 < kIters) {
            buf ^= 1;
            As[buf][k4 + 0][lrow] = aReg.x; As[buf][k4 + 1][lrow] = aReg.y;
            As[buf][k4 + 2][lrow] = aReg.z; As[buf][k4 + 3][lrow] = aReg.w;
            Bs[buf][k4 + 0][lrow] = bReg.x; Bs[buf][k4 + 1][lrow] = bReg.y;
            Bs[buf][k4 + 2][lrow] = bReg.z; Bs[buf][k4 + 3][lrow] = bReg.w;
            __syncthreads();
        }
    }

    #pragma unroll
    for (int r = 0; r < 8; r++) {
        const int row = m0 + ty * 8 + r;
        float* cp = C + (size_t)row * N + n0 + tx * 8;
        #pragma unroll
        for (int c = 0; c < 8; c++) {
            float v = acc[r][c];
            if (bias) v += bias[n0 + tx * 8 + c];
            cp[c] = v;
        }
    }
}

// ---------------------------------------------------------------------------
// RoPE applied in-place to q and k parts of g_qkv.
// Layout: qkv[((n*T + t)*3 + p)*D + h*64 + d], p in {0(q),1(k)}.
// Pair (d, d+32), d in [0,32): x1'=x1*c - x2*s ; x2'=x2*c + x1*s
// freq = t * 10000^{-(2d)/64}
// ---------------------------------------------------------------------------
__global__ __launch_bounds__(256) void rope_kernel(float* __restrict__ qkv)
{
    int idx = blockIdx.x * blockDim.x + threadIdx.x;   // exactly NB*TT*2*HH*32 threads
    int d  = idx & 31;
    int h  = (idx >> 5) & 15;
    int p  = (idx >> 9) & 1;
    int nt = idx >> 10;                 // 0..NB*TT-1 (exact)
    int t  = nt & (TT - 1);

    float inv = powf(10000.0f, -(float)(2 * d) / 64.0f);
    float fr  = (float)t * inv;
    float c, s;
    sincosf(fr, &s, &c);

    size_t base = ((size_t)nt * 3 + p) * DD + h * HDD + d;
    float x1 = qkv[base];
    float x2 = qkv[base + 32];
    qkv[base]      = x1 * c - x2 * s;
    qkv[base + 32] = x2 * c + x1 * s;
}

// ---------------------------------------------------------------------------
// Banded attention, flash-style online softmax.
// Block = (qtile of 128, head, batch). 128 threads, 1 thread = 1 query row.
// Keys tiled 32 at a time through smem (K and V, 64 dims each).
// ---------------------------------------------------------------------------
__global__ __launch_bounds__(128) void attn_kernel(
    const float* __restrict__ qkv, float* __restrict__ attn)
{
    const int qt = blockIdx.x;       // 0..T/128-1
    const int h  = blockIdx.y;       // 0..15
    const int n  = blockIdx.z;       // 0..1
    const int tq = threadIdx.x;      // 0..127
    const int i  = qt * 128 + tq;    // query position
    const int i0 = qt * 128;

    __shared__ float4 Ks[32][16];
    __shared__ float4 Vs[32][16];

    // load this query's 64-dim vector
    const float* qp = qkv + (((size_t)(n * TT + i) * 3 + 0)) * DD + h * HDD;
    float4 qv[16];
    #pragma unroll
    for (int x = 0; x < 16; x++) qv[x] = ((const float4*)qp)[x];

    float4 acc[16];
    #pragma unroll
    for (int x = 0; x < 16; x++) acc[x] = make_float4(0.f, 0.f, 0.f, 0.f);
    float m = -1e30f, l = 0.0f;

    const int klo = max(0, i0 - WL);
    const int khi = min(TT - 1, i0 + 127 + WR);

    for (int ks = klo; ks <= khi; ks += 32) {
        __syncthreads();
        // cooperative load: 32 keys x 16 float4, K and V
        for (int e = tq; e < 512; e += 128) {
            int row = e >> 4, c4 = e & 15;
            int sg = ks + row;
            float4 kk = make_float4(0.f, 0.f, 0.f, 0.f);
            float4 vv = kk;
            if (sg <= khi) {
                size_t b = ((size_t)(n * TT + sg) * 3) * DD + h * HDD;
                kk = ((const float4*)(qkv + b + DD))[c4];       // K part
                vv = ((const float4*)(qkv + b + 2 * DD))[c4];   // V part
            }
            Ks[row][c4] = kk;
            Vs[row][c4] = vv;
        }
        __syncthreads();

        const int jmax = min(32, khi - ks + 1);
        for (int j = 0; j < jmax; j++) {
            const int sg = ks + j;
            const bool valid = (sg >= i - WL) && (sg <= i + WR);
            float s = 0.0f;
            #pragma unroll
            for (int x = 0; x < 16; x++) {
                float4 kk = Ks[j][x];
                s = fmaf(qv[x].x, kk.x, s);
                s = fmaf(qv[x].y, kk.y, s);
                s = fmaf(qv[x].z, kk.z, s);
                s = fmaf(qv[x].w, kk.w, s);
            }
            s *= 0.125f;  // 1/sqrt(64)
            if (valid) {
                if (s > m) {
                    float corr = expf(m - s);
                    l *= corr;
                    #pragma unroll
                    for (int x = 0; x < 16; x++) {
                        acc[x].x *= corr; acc[x].y *= corr;
                        acc[x].z *= corr; acc[x].w *= corr;
                    }
                    m = s;
                }
                float p = expf(s - m);
                l += p;
                #pragma unroll
                for (int x = 0; x < 16; x++) {
                    float4 vv = Vs[j][x];
                    acc[x].x = fmaf(p, vv.x, acc[x].x);
                    acc[x].y = fmaf(p, vv.y, acc[x].y);
                    acc[x].z = fmaf(p, vv.z, acc[x].z);
                    acc[x].w = fmaf(p, vv.w, acc[x].w);
                }
            }
        }
    }

    const float inv_l = 1.0f / l;
    float* op = attn + ((size_t)(n * TT + i)) * DD + h * HDD;
    #pragma unroll
    for (int x = 0; x < 16; x++) {
        float4 v = acc[x];
        v.x *= inv_l; v.y *= inv_l; v.z *= inv_l; v.w *= inv_l;
        ((float4*)op)[x] = v;
    }
}

// ---------------------------------------------------------------------------
extern "C" void kernel_launch(void* const* d_in, const int* in_sizes, int n_in,
                              void* d_out, int out_size)
{
    const float* x     = (const float*)d_in[0];   // [N,T,D]
    const float* w_qkv = (const float*)d_in[1];   // [3D, D]
    const float* w_out = (const float*)d_in[2];   // [D, D]
    const float* b_out = (const float*)d_in[3];   // [D]
    float* out = (float*)d_out;                   // [N,T,D]

    float* qkv  = nullptr;
    float* attn = nullptr;
    cudaGetSymbolAddress((void**)&qkv,  g_qkv);
    cudaGetSymbolAddress((void**)&attn, g_attn);

    const int M = NB * TT;  // 4096

    // 1) qkv = x @ w_qkv^T
    {
        dim3 grid(3 * DD / 128, M / 128);
        sgemm_nt<<<grid, 256>>>(x, w_qkv, nullptr, qkv, M, 3 * DD, DD);
    }
    // 2) RoPE on q,k (in place)
    {
        int total = NB * TT * 2 * HH * 32;   // 4,194,304
        rope_kernel<<<total / 256, 256>>>(qkv);
    }
    // 3) banded attention
    {
        dim3 grid(TT / 128, HH, NB);
        attn_kernel<<<grid, 128>>>(qkv, attn);
    }
    // 4) out = attn @ w_out^T + b_out
    {
        dim3 grid(DD / 128, M / 128);
        sgemm_nt<<<grid, 256>>>(attn, w_out, b_out, out, M, DD, DD);
    }
}

// round 5
// speedup vs baseline: 1.2660x; 1.2660x over previous
#include <cuda_runtime.h>
#include <math.h>
#include <stdint.h>

#define NB   2
#define TT   2048
#define DD   1024
#define HH   16
#define HDD  64
#define WL   127
#define WR   128

#define SST  36   // smem row stride in floats (conflict-free fragment gathers)

// Scratch (allocation-free)
__device__ float g_qkv[(size_t)NB * TT * 3 * DD];   // [N,T,3,D]
__device__ float g_attn[(size_t)NB * TT * DD];      // [N,T,D]

// ---------------------------------------------------------------------------
__device__ __forceinline__ uint32_t smem_u32(const void* p) {
    uint32_t r;
    asm("{ .reg .u64 t; cvta.to.shared.u64 t, %1; cvt.u32.u64 %0, t; }"
        : "=r"(r) : "l"(p));
    return r;
}
__device__ __forceinline__ void cp_async16(uint32_t s, const void* g) {
    asm volatile("cp.async.cg.shared.global [%0], [%1], 16;" :: "r"(s), "l"(g));
}
__device__ __forceinline__ void cp_commit() {
    asm volatile("cp.async.commit_group;" ::: "memory");
}
template <int N_> __device__ __forceinline__ void cp_wait() {
    asm volatile("cp.async.wait_group %0;" :: "n"(N_) : "memory");
}

// 3xTF32 split: x ~= hi + lo, both tf32-representable
__device__ __forceinline__ uint32_t f2tf32(float x) {
    uint32_t r;
    asm("cvt.rna.tf32.f32 %0, %1;" : "=r"(r) : "f"(x));
    return r;
}
__device__ __forceinline__ void split_tf32(float x, uint32_t& hi, uint32_t& lo) {
    hi = f2tf32(x);
    lo = f2tf32(x - __uint_as_float(hi));
}

#define MMA_TF32(ACC, A0, A1, A2, A3, B0, B1)                                  \
    asm volatile(                                                              \
        "mma.sync.aligned.m16n8k8.row.col.f32.tf32.tf32.f32 "                  \
        "{%0,%1,%2,%3}, {%4,%5,%6,%7}, {%8,%9}, {%0,%1,%2,%3};"                \
        : "+f"(ACC[0]), "+f"(ACC[1]), "+f"(ACC[2]), "+f"(ACC[3])               \
        : "r"(A0), "r"(A1), "r"(A2), "r"(A3), "r"(B0), "r"(B1))

// ---------------------------------------------------------------------------
// 3xTF32 mma.sync GEMM: C[m,n] = sum_k A[m,k]*B[n,k] (+ bias[n]), ~fp32 accurate
// A:[M,K], B:[N,K] row-major (K contiguous). M%128==0, N%128==0, K%32==0.
// 256 threads, CTA tile 128x128, BK=32, double-buffered cp.async staging.
// ---------------------------------------------------------------------------
__global__ __launch_bounds__(256) void gemm_tf32(
    const float* __restrict__ A, const float* __restrict__ B,
    const float* __restrict__ bias, float* __restrict__ C,
    int M, int N, int K)
{
    extern __shared__ float smem[];           // 2 bufs x (A:128*SST + B:128*SST)
    const int BUF = 128 * SST;

    const int tid  = threadIdx.x;
    const int wid  = tid >> 5;
    const int lane = tid & 31;
    const int g    = lane >> 2;               // 0..7
    const int t    = lane & 3;                // 0..3
    const int warpM = (wid >> 2) * 64;        // 0 or 64
    const int warpN = (wid & 3) * 32;         // 0,32,64,96
    const int m0 = blockIdx.y * 128;
    const int n0 = blockIdx.x * 128;

    const uint32_t sbase = smem_u32(smem);

    auto load_tile = [&](int kt, int b) {
        const uint32_t dst = sbase + (uint32_t)b * (2u * BUF * 4u);
        const float* gA = A + (size_t)m0 * K + kt * 32;
        const float* gB = B + (size_t)n0 * K + kt * 32;
        #pragma unroll
        for (int c = 0; c < 4; c++) {
            int idx = tid + c * 256;
            int row = idx >> 3, j = idx & 7;
            cp_async16(dst + (uint32_t)(row * SST + j * 4) * 4u,
                       gA + (size_t)row * K + j * 4);
            cp_async16(dst + (uint32_t)(BUF + row * SST + j * 4) * 4u,
                       gB + (size_t)row * K + j * 4);
        }
        cp_commit();
    };

    float acc[4][4][4];
    #pragma unroll
    for (int mi = 0; mi < 4; mi++)
        #pragma unroll
        for (int ni = 0; ni < 4; ni++)
            #pragma unroll
            for (int r = 0; r < 4; r++) acc[mi][ni][r] = 0.0f;

    const int ktiles = K / 32;
    load_tile(0, 0);

    for (int kt = 0; kt < ktiles; kt++) {
        const int buf = kt & 1;
        if (kt + 1 < ktiles) { load_tile(kt + 1, buf ^ 1); cp_wait<1>(); }
        else                 { cp_wait<0>(); }
        __syncthreads();

        const float* As = smem + buf * 2 * BUF;
        const float* Bs = As + BUF;

        #pragma unroll
        for (int s = 0; s < 4; s++) {
            uint32_t ah[4][4], al[4][4], bh[4][2], bl[4][2];
            #pragma unroll
            for (int mi = 0; mi < 4; mi++) {
                const int r = warpM + mi * 16 + g;
                split_tf32(As[r       * SST + s * 8 + t],     ah[mi][0], al[mi][0]);
                split_tf32(As[(r + 8) * SST + s * 8 + t],     ah[mi][1], al[mi][1]);
                split_tf32(As[r       * SST + s * 8 + t + 4], ah[mi][2], al[mi][2]);
                split_tf32(As[(r + 8) * SST + s * 8 + t + 4], ah[mi][3], al[mi][3]);
            }
            #pragma unroll
            for (int ni = 0; ni < 4; ni++) {
                const int r = warpN + ni * 8 + g;
                split_tf32(Bs[r * SST + s * 8 + t],     bh[ni][0], bl[ni][0]);
                split_tf32(Bs[r * SST + s * 8 + t + 4], bh[ni][1], bl[ni][1]);
            }
            #pragma unroll
            for (int mi = 0; mi < 4; mi++)
                #pragma unroll
                for (int ni = 0; ni < 4; ni++) {
                    // small cross-terms first, then the big term
                    MMA_TF32(acc[mi][ni], al[mi][0], al[mi][1], al[mi][2], al[mi][3],
                             bh[ni][0], bh[ni][1]);
                    MMA_TF32(acc[mi][ni], ah[mi][0], ah[mi][1], ah[mi][2], ah[mi][3],
                             bl[ni][0], bl[ni][1]);
                    MMA_TF32(acc[mi][ni], ah[mi][0], ah[mi][1], ah[mi][2], ah[mi][3],
                             bh[ni][0], bh[ni][1]);
                }
        }
        __syncthreads();
    }

    // epilogue
    #pragma unroll
    for (int mi = 0; mi < 4; mi++) {
        const int row = m0 + warpM + mi * 16 + g;
        #pragma unroll
        for (int ni = 0; ni < 4; ni++) {
            const int col = n0 + warpN + ni * 8 + t * 2;
            float bx = 0.f, by = 0.f;
            if (bias) { bx = bias[col]; by = bias[col + 1]; }
            float2 v0 = make_float2(acc[mi][ni][0] + bx, acc[mi][ni][1] + by);
            float2 v1 = make_float2(acc[mi][ni][2] + bx, acc[mi][ni][3] + by);
            *(float2*)(C + (size_t)row * N + col)       = v0;
            *(float2*)(C + (size_t)(row + 8) * N + col) = v1;
        }
    }
}

// ---------------------------------------------------------------------------
// RoPE in-place on q,k of g_qkv.
// ---------------------------------------------------------------------------
__global__ __launch_bounds__(256) void rope_kernel(float* __restrict__ qkv)
{
    int idx = blockIdx.x * blockDim.x + threadIdx.x;
    int d  = idx & 31;
    int h  = (idx >> 5) & 15;
    int p  = (idx >> 9) & 1;
    int nt = idx >> 10;
    int t  = nt & (TT - 1);

    float inv = exp2f(-0.41524101186092029f * (float)d);  // 10000^{-2d/64}
    float fr  = (float)t * inv;
    float c, s;
    sincosf(fr, &s, &c);

    size_t base = ((size_t)nt * 3 + p) * DD + h * HDD + d;
    float x1 = qkv[base];
    float x2 = qkv[base + 32];
    qkv[base]      = x1 * c - x2 * s;
    qkv[base + 32] = x2 * c + x1 * s;
}

// ---------------------------------------------------------------------------
// Banded attention, flash-style online softmax.
// ---------------------------------------------------------------------------
__global__ __launch_bounds__(128) void attn_kernel(
    const float* __restrict__ qkv, float* __restrict__ attn)
{
    const int qt = blockIdx.x;
    const int h  = blockIdx.y;
    const int n  = blockIdx.z;
    const int tq = threadIdx.x;
    const int i  = qt * 128 + tq;
    const int i0 = qt * 128;

    __shared__ float4 Ks[32][16];
    __shared__ float4 Vs[32][16];

    const float* qp = qkv + (((size_t)(n * TT + i) * 3 + 0)) * DD + h * HDD;
    float4 qv[16];
    #pragma unroll
    for (int x = 0; x < 16; x++) qv[x] = ((const float4*)qp)[x];

    float4 acc[16];
    #pragma unroll
    for (int x = 0; x < 16; x++) acc[x] = make_float4(0.f, 0.f, 0.f, 0.f);
    float m = -1e30f, l = 0.0f;

    const int klo = max(0, i0 - WL);
    const int khi = min(TT - 1, i0 + 127 + WR);

    for (int ks = klo; ks <= khi; ks += 32) {
        __syncthreads();
        for (int e = tq; e < 512; e += 128) {
            int row = e >> 4, c4 = e & 15;
            int sg = ks + row;
            float4 kk = make_float4(0.f, 0.f, 0.f, 0.f);
            float4 vv = kk;
            if (sg <= khi) {
                size_t b = ((size_t)(n * TT + sg) * 3) * DD + h * HDD;
                kk = ((const float4*)(qkv + b + DD))[c4];
                vv = ((const float4*)(qkv + b + 2 * DD))[c4];
            }
            Ks[row][c4] = kk;
            Vs[row][c4] = vv;
        }
        __syncthreads();

        const int jmax = min(32, khi - ks + 1);
        for (int j = 0; j < jmax; j++) {
            const int sg = ks + j;
            const bool valid = (sg >= i - WL) && (sg <= i + WR);
            float s = 0.0f;
            #pragma unroll
            for (int x = 0; x < 16; x++) {
                float4 kk = Ks[j][x];
                s = fmaf(qv[x].x, kk.x, s);
                s = fmaf(qv[x].y, kk.y, s);
                s = fmaf(qv[x].z, kk.z, s);
                s = fmaf(qv[x].w, kk.w, s);
            }
            s *= 0.125f;
            if (valid) {
                if (s > m) {
                    float corr = expf(m - s);
                    l *= corr;
                    #pragma unroll
                    for (int x = 0; x < 16; x++) {
                        acc[x].x *= corr; acc[x].y *= corr;
                        acc[x].z *= corr; acc[x].w *= corr;
                    }
                    m = s;
                }
                float p = expf(s - m);
                l += p;
                #pragma unroll
                for (int x = 0; x < 16; x++) {
                    float4 vv = Vs[j][x];
                    acc[x].x = fmaf(p, vv.x, acc[x].x);
                    acc[x].y = fmaf(p, vv.y, acc[x].y);
                    acc[x].z = fmaf(p, vv.z, acc[x].z);
                    acc[x].w = fmaf(p, vv.w, acc[x].w);
                }
            }
        }
    }

    const float inv_l = 1.0f / l;
    float* op = attn + ((size_t)(n * TT + i)) * DD + h * HDD;
    #pragma unroll
    for (int x = 0; x < 16; x++) {
        float4 v = acc[x];
        v.x *= inv_l; v.y *= inv_l; v.z *= inv_l; v.w *= inv_l;
        ((float4*)op)[x] = v;
    }
}

// ---------------------------------------------------------------------------
extern "C" void kernel_launch(void* const* d_in, const int* in_sizes, int n_in,
                              void* d_out, int out_size)
{
    const float* x     = (const float*)d_in[0];
    const float* w_qkv = (const float*)d_in[1];
    const float* w_out = (const float*)d_in[2];
    const float* b_out = (const float*)d_in[3];
    float* out = (float*)d_out;

    float* qkv  = nullptr;
    float* attn = nullptr;
    cudaGetSymbolAddress((void**)&qkv,  g_qkv);
    cudaGetSymbolAddress((void**)&attn, g_attn);

    const int M = NB * TT;                       // 4096
    const int SMEM_GEMM = 2 * 2 * 128 * SST * 4; // 73728 bytes

    cudaFuncSetAttribute(gemm_tf32, cudaFuncAttributeMaxDynamicSharedMemorySize,
                         SMEM_GEMM);

    // 1) qkv = x @ w_qkv^T   (3xTF32 tensor cores)
    {
        dim3 grid(3 * DD / 128, M / 128);
        gemm_tf32<<<grid, 256, SMEM_GEMM>>>(x, w_qkv, nullptr, qkv, M, 3 * DD, DD);
    }
    // 2) RoPE
    {
        int total = NB * TT * 2 * HH * 32;
        rope_kernel<<<total / 256, 256>>>(qkv);
    }
    // 3) banded attention
    {
        dim3 grid(TT / 128, HH, NB);
        attn_kernel<<<grid, 128>>>(qkv, attn);
    }
    // 4) out = attn @ w_out^T + b_out
    {
        dim3 grid(DD / 128, M / 128);
        gemm_tf32<<<grid, 256, SMEM_GEMM>>>(attn, w_out, b_out, out, M, DD, DD);
    }
}

// round 6
// speedup vs baseline: 1.2836x; 1.0139x over previous
#include <cuda_runtime.h>
#include <math.h>
#include <stdint.h>

#define NB   2
#define TT   2048
#define DD   1024
#define HH   16
#define HDD  64
#define WL   127
#define WR   128

#define SST  36   // smem row stride in floats (conflict-free fragment gathers)

// Scratch (allocation-free)
__device__ float    g_qkv[(size_t)NB * TT * 3 * DD];   // [N,T,3,D]
__device__ float    g_attn[(size_t)NB * TT * DD];      // [N,T,D]
__device__ uint32_t g_ahi[(size_t)NB * TT * DD];       // A operand hi plane (tf32 bits)
__device__ uint32_t g_alo[(size_t)NB * TT * DD];       // A operand lo plane
__device__ uint32_t g_bhi[(size_t)3 * DD * DD];        // B operand hi plane
__device__ uint32_t g_blo[(size_t)3 * DD * DD];        // B operand lo plane

// ---------------------------------------------------------------------------
__device__ __forceinline__ uint32_t smem_u32(const void* p) {
    uint32_t r;
    asm("{ .reg .u64 t; cvta.to.shared.u64 t, %1; cvt.u32.u64 %0, t; }"
        : "=r"(r) : "l"(p));
    return r;
}
__device__ __forceinline__ void cp_async16(uint32_t s, const void* g) {
    asm volatile("cp.async.cg.shared.global [%0], [%1], 16;" :: "r"(s), "l"(g));
}
__device__ __forceinline__ void cp_commit() {
    asm volatile("cp.async.commit_group;" ::: "memory");
}
template <int N_> __device__ __forceinline__ void cp_wait() {
    asm volatile("cp.async.wait_group %0;" :: "n"(N_) : "memory");
}

__device__ __forceinline__ uint32_t f2tf32(float x) {
    uint32_t r;
    asm("cvt.rna.tf32.f32 %0, %1;" : "=r"(r) : "f"(x));
    return r;
}

#define MMA_TF32(ACC, A0, A1, A2, A3, B0, B1)                                  \
    asm volatile(                                                              \
        "mma.sync.aligned.m16n8k8.row.col.f32.tf32.tf32.f32 "                  \
        "{%0,%1,%2,%3}, {%4,%5,%6,%7}, {%8,%9}, {%0,%1,%2,%3};"                \
        : "+f"(ACC[0]), "+f"(ACC[1]), "+f"(ACC[2]), "+f"(ACC[3])               \
        : "r"(A0), "r"(A1), "r"(A2), "r"(A3), "r"(B0), "r"(B1))

// ---------------------------------------------------------------------------
// Elementwise split: x -> (hi, lo) tf32 planes.  n must be a multiple of 4.
// ---------------------------------------------------------------------------
__global__ __launch_bounds__(256) void split_kernel(
    const float* __restrict__ in, uint32_t* __restrict__ hi,
    uint32_t* __restrict__ lo, int n4)
{
    int i = blockIdx.x * blockDim.x + threadIdx.x;
    if (i >= n4) return;
    float4 v = ((const float4*)in)[i];
    uint4 h, l;
    h.x = f2tf32(v.x); l.x = f2tf32(v.x - __uint_as_float(h.x));
    h.y = f2tf32(v.y); l.y = f2tf32(v.y - __uint_as_float(h.y));
    h.z = f2tf32(v.z); l.z = f2tf32(v.z - __uint_as_float(h.z));
    h.w = f2tf32(v.w); l.w = f2tf32(v.w - __uint_as_float(h.w));
    ((uint4*)hi)[i] = h;
    ((uint4*)lo)[i] = l;
}

// ---------------------------------------------------------------------------
// 3xTF32 mma.sync GEMM on pre-split hi/lo planes:
//   C[m,n] = sum_k A[m,k]*B[n,k] (+ bias[n]),  ~fp32 accurate
// Planes: [M,K]/[N,K] row-major tf32 bit patterns. M%128==0,N%128==0,K%32==0.
// 256 threads, CTA tile 128x128, BK=32, double-buffered cp.async staging.
// Mainloop is pure LDS + HMMA (no cvt).
// ---------------------------------------------------------------------------
__global__ __launch_bounds__(256) void gemm_3xtf32(
    const uint32_t* __restrict__ Ahi, const uint32_t* __restrict__ Alo,
    const uint32_t* __restrict__ Bhi, const uint32_t* __restrict__ Blo,
    const float* __restrict__ bias, float* __restrict__ C,
    int M, int N, int K)
{
    extern __shared__ uint32_t smem[];        // 2 bufs x 4 planes x 128*SST
    const int BUF = 128 * SST;                // u32 per plane tile

    const int tid  = threadIdx.x;
    const int wid  = tid >> 5;
    const int lane = tid & 31;
    const int g    = lane >> 2;               // 0..7
    const int t    = lane & 3;                // 0..3
    const int warpM = (wid >> 2) * 64;        // 0 or 64
    const int warpN = (wid & 3) * 32;         // 0,32,64,96
    const int m0 = blockIdx.y * 128;
    const int n0 = blockIdx.x * 128;

    const uint32_t sbase = smem_u32(smem);

    // stage 4 planes of one BK=32 tile into buffer b
    auto load_tile = [&](int kt, int b) {
        const uint32_t dst = sbase + (uint32_t)b * (4u * BUF * 4u);
        const uint32_t* gp[4];
        gp[0] = Ahi + (size_t)m0 * K + kt * 32;
        gp[1] = Alo + (size_t)m0 * K + kt * 32;
        gp[2] = Bhi + (size_t)n0 * K + kt * 32;
        gp[3] = Blo + (size_t)n0 * K + kt * 32;
        #pragma unroll
        for (int c = 0; c < 4; c++) {
            int idx = tid + c * 256;          // 0..1023
            int row = idx >> 3, j = idx & 7;
            uint32_t soff = (uint32_t)(row * SST + j * 4) * 4u;
            #pragma unroll
            for (int pl = 0; pl < 4; pl++)
                cp_async16(dst + pl * (BUF * 4u) + soff,
                           gp[pl] + (size_t)row * K + j * 4);
        }
        cp_commit();
    };

    float acc[4][4][4];
    #pragma unroll
    for (int mi = 0; mi < 4; mi++)
        #pragma unroll
        for (int ni = 0; ni < 4; ni++)
            #pragma unroll
            for (int r = 0; r < 4; r++) acc[mi][ni][r] = 0.0f;

    const int ktiles = K / 32;
    load_tile(0, 0);

    for (int kt = 0; kt < ktiles; kt++) {
        const int buf = kt & 1;
        if (kt + 1 < ktiles) { load_tile(kt + 1, buf ^ 1); cp_wait<1>(); }
        else                 { cp_wait<0>(); }
        __syncthreads();

        const uint32_t* Ah = smem + buf * 4 * BUF;
        const uint32_t* Al = Ah + BUF;
        const uint32_t* Bh = Al + BUF;
        const uint32_t* Bl = Bh + BUF;

        #pragma unroll
        for (int s = 0; s < 4; s++) {
            uint32_t ah[4][4], al[4][4], bh[4][2], bl[4][2];
            #pragma unroll
            for (int mi = 0; mi < 4; mi++) {
                const int r = warpM + mi * 16 + g;
                const int o0 = r * SST + s * 8 + t;
                const int o1 = (r + 8) * SST + s * 8 + t;
                ah[mi][0] = Ah[o0];     ah[mi][1] = Ah[o1];
                ah[mi][2] = Ah[o0 + 4]; ah[mi][3] = Ah[o1 + 4];
                al[mi][0] = Al[o0];     al[mi][1] = Al[o1];
                al[mi][2] = Al[o0 + 4]; al[mi][3] = Al[o1 + 4];
            }
            #pragma unroll
            for (int ni = 0; ni < 4; ni++) {
                const int o = (warpN + ni * 8 + g) * SST + s * 8 + t;
                bh[ni][0] = Bh[o]; bh[ni][1] = Bh[o + 4];
                bl[ni][0] = Bl[o]; bl[ni][1] = Bl[o + 4];
            }
            #pragma unroll
            for (int mi = 0; mi < 4; mi++)
                #pragma unroll
                for (int ni = 0; ni < 4; ni++) {
                    MMA_TF32(acc[mi][ni], al[mi][0], al[mi][1], al[mi][2], al[mi][3],
                             bh[ni][0], bh[ni][1]);
                    MMA_TF32(acc[mi][ni], ah[mi][0], ah[mi][1], ah[mi][2], ah[mi][3],
                             bl[ni][0], bl[ni][1]);
                    MMA_TF32(acc[mi][ni], ah[mi][0], ah[mi][1], ah[mi][2], ah[mi][3],
                             bh[ni][0], bh[ni][1]);
                }
        }
        __syncthreads();
    }

    // epilogue
    #pragma unroll
    for (int mi = 0; mi < 4; mi++) {
        const int row = m0 + warpM + mi * 16 + g;
        #pragma unroll
        for (int ni = 0; ni < 4; ni++) {
            const int col = n0 + warpN + ni * 8 + t * 2;
            float bx = 0.f, by = 0.f;
            if (bias) { bx = bias[col]; by = bias[col + 1]; }
            float2 v0 = make_float2(acc[mi][ni][0] + bx, acc[mi][ni][1] + by);
            float2 v1 = make_float2(acc[mi][ni][2] + bx, acc[mi][ni][3] + by);
            *(float2*)(C + (size_t)row * N + col)       = v0;
            *(float2*)(C + (size_t)(row + 8) * N + col) = v1;
        }
    }
}

// ---------------------------------------------------------------------------
// RoPE in-place on q,k of g_qkv.
// ---------------------------------------------------------------------------
__global__ __launch_bounds__(256) void rope_kernel(float* __restrict__ qkv)
{
    int idx = blockIdx.x * blockDim.x + threadIdx.x;
    int d  = idx & 31;
    int h  = (idx >> 5) & 15;
    int p  = (idx >> 9) & 1;
    int nt = idx >> 10;
    int t  = nt & (TT - 1);

    float inv = exp2f(-0.41524101186092029f * (float)d);  // 10000^{-2d/64}
    float fr  = (float)t * inv;
    float c, s;
    sincosf(fr, &s, &c);

    size_t base = ((size_t)nt * 3 + p) * DD + h * HDD + d;
    float x1 = qkv[base];
    float x2 = qkv[base + 32];
    qkv[base]      = x1 * c - x2 * s;
    qkv[base + 32] = x2 * c + x1 * s;
}

// ---------------------------------------------------------------------------
// Banded attention, flash-style online softmax.
// ---------------------------------------------------------------------------
__global__ __launch_bounds__(128) void attn_kernel(
    const float* __restrict__ qkv, float* __restrict__ attn)
{
    const int qt = blockIdx.x;
    const int h  = blockIdx.y;
    const int n  = blockIdx.z;
    const int tq = threadIdx.x;
    const int i  = qt * 128 + tq;
    const int i0 = qt * 128;

    __shared__ float4 Ks[32][16];
    __shared__ float4 Vs[32][16];

    const float* qp = qkv + (((size_t)(n * TT + i) * 3 + 0)) * DD + h * HDD;
    float4 qv[16];
    #pragma unroll
    for (int x = 0; x < 16; x++) qv[x] = ((const float4*)qp)[x];

    float4 acc[16];
    #pragma unroll
    for (int x = 0; x < 16; x++) acc[x] = make_float4(0.f, 0.f, 0.f, 0.f);
    float m = -1e30f, l = 0.0f;

    const int klo = max(0, i0 - WL);
    const int khi = min(TT - 1, i0 + 127 + WR);

    for (int ks = klo; ks <= khi; ks += 32) {
        __syncthreads();
        for (int e = tq; e < 512; e += 128) {
            int row = e >> 4, c4 = e & 15;
            int sg = ks + row;
            float4 kk = make_float4(0.f, 0.f, 0.f, 0.f);
            float4 vv = kk;
            if (sg <= khi) {
                size_t b = ((size_t)(n * TT + sg) * 3) * DD + h * HDD;
                kk = ((const float4*)(qkv + b + DD))[c4];
                vv = ((const float4*)(qkv + b + 2 * DD))[c4];
            }
            Ks[row][c4] = kk;
            Vs[row][c4] = vv;
        }
        __syncthreads();

        const int jmax = min(32, khi - ks + 1);
        for (int j = 0; j < jmax; j++) {
            const int sg = ks + j;
            const bool valid = (sg >= i - WL) && (sg <= i + WR);
            float s = 0.0f;
            #pragma unroll
            for (int x = 0; x < 16; x++) {
                float4 kk = Ks[j][x];
                s = fmaf(qv[x].x, kk.x, s);
                s = fmaf(qv[x].y, kk.y, s);
                s = fmaf(qv[x].z, kk.z, s);
                s = fmaf(qv[x].w, kk.w, s);
            }
            s *= 0.125f;
            if (valid) {
                if (s > m) {
                    float corr = expf(m - s);
                    l *= corr;
                    #pragma unroll
                    for (int x = 0; x < 16; x++) {
                        acc[x].x *= corr; acc[x].y *= corr;
                        acc[x].z *= corr; acc[x].w *= corr;
                    }
                    m = s;
                }
                float p = expf(s - m);
                l += p;
                #pragma unroll
                for (int x = 0; x < 16; x++) {
                    float4 vv = Vs[j][x];
                    acc[x].x = fmaf(p, vv.x, acc[x].x);
                    acc[x].y = fmaf(p, vv.y, acc[x].y);
                    acc[x].z = fmaf(p, vv.z, acc[x].z);
                    acc[x].w = fmaf(p, vv.w, acc[x].w);
                }
            }
        }
    }

    const float inv_l = 1.0f / l;
    float* op = attn + ((size_t)(n * TT + i)) * DD + h * HDD;
    #pragma unroll
    for (int x = 0; x < 16; x++) {
        float4 v = acc[x];
        v.x *= inv_l; v.y *= inv_l; v.z *= inv_l; v.w *= inv_l;
        ((float4*)op)[x] = v;
    }
}

// ---------------------------------------------------------------------------
extern "C" void kernel_launch(void* const* d_in, const int* in_sizes, int n_in,
                              void* d_out, int out_size)
{
    const float* x     = (const float*)d_in[0];
    const float* w_qkv = (const float*)d_in[1];
    const float* w_out = (const float*)d_in[2];
    const float* b_out = (const float*)d_in[3];
    float* out = (float*)d_out;

    float *qkv = nullptr, *attn = nullptr;
    uint32_t *ahi = nullptr, *alo = nullptr, *bhi = nullptr, *blo = nullptr;
    cudaGetSymbolAddress((void**)&qkv,  g_qkv);
    cudaGetSymbolAddress((void**)&attn, g_attn);
    cudaGetSymbolAddress((void**)&ahi,  g_ahi);
    cudaGetSymbolAddress((void**)&alo,  g_alo);
    cudaGetSymbolAddress((void**)&bhi,  g_bhi);
    cudaGetSymbolAddress((void**)&blo,  g_blo);

    const int M = NB * TT;                         // 4096
    const int SMEM_GEMM = 2 * 4 * 128 * SST * 4;   // 147456 bytes

    cudaFuncSetAttribute(gemm_3xtf32, cudaFuncAttributeMaxDynamicSharedMemorySize,
                         SMEM_GEMM);

    // split x and w_qkv into tf32 hi/lo planes
    {
        int n4 = M * DD / 4;
        split_kernel<<<(n4 + 255) / 256, 256>>>(x, ahi, alo, n4);
        n4 = 3 * DD * DD / 4;
        split_kernel<<<(n4 + 255) / 256, 256>>>(w_qkv, bhi, blo, n4);
    }
    // 1) qkv = x @ w_qkv^T
    {
        dim3 grid(3 * DD / 128, M / 128);
        gemm_3xtf32<<<grid, 256, SMEM_GEMM>>>(ahi, alo, bhi, blo, nullptr, qkv,
                                              M, 3 * DD, DD);
    }
    // 2) RoPE
    {
        int total = NB * TT * 2 * HH * 32;
        rope_kernel<<<total / 256, 256>>>(qkv);
    }
    // 3) banded attention
    {
        dim3 grid(TT / 128, HH, NB);
        attn_kernel<<<grid, 128>>>(qkv, attn);
    }
    // split attn and w_out
    {
        int n4 = M * DD / 4;
        split_kernel<<<(n4 + 255) / 256, 256>>>(attn, ahi, alo, n4);
        n4 = DD * DD / 4;
        split_kernel<<<(n4 + 255) / 256, 256>>>(w_out, bhi, blo, n4);
    }
    // 4) out = attn @ w_out^T + b_out
    {
        dim3 grid(DD / 128, M / 128);
        gemm_3xtf32<<<grid, 256, SMEM_GEMM>>>(ahi, alo, bhi, blo, b_out, out,
                                              M, DD, DD);
    }
}

// round 7
// speedup vs baseline: 1.3025x; 1.0147x over previous
#include <cuda_runtime.h>
#include <math.h>
#include <stdint.h>

#define NB   2
#define TT   2048
#define DD   1024
#define HH   16
#define HDD  64
#define WL   127
#define WR   128

#define SST  36   // smem row stride in floats (rows land on distinct bank groups)

// Scratch (allocation-free)
__device__ float    g_qkv[(size_t)NB * TT * 3 * DD];   // [N,T,3,D]
__device__ float    g_attn[(size_t)NB * TT * DD];      // [N,T,D]
__device__ uint32_t g_ahi[(size_t)NB * TT * DD];       // A hi plane (tf32 bits)
__device__ uint32_t g_alo[(size_t)NB * TT * DD];       // A lo plane
__device__ uint32_t g_bhi[(size_t)3 * DD * DD];        // B hi plane
__device__ uint32_t g_blo[(size_t)3 * DD * DD];        // B lo plane

// ---------------------------------------------------------------------------
__device__ __forceinline__ uint32_t smem_u32(const void* p) {
    uint32_t r;
    asm("{ .reg .u64 t; cvta.to.shared.u64 t, %1; cvt.u32.u64 %0, t; }"
        : "=r"(r) : "l"(p));
    return r;
}
__device__ __forceinline__ void cp_async16(uint32_t s, const void* g) {
    asm volatile("cp.async.cg.shared.global [%0], [%1], 16;" :: "r"(s), "l"(g));
}
__device__ __forceinline__ void cp_commit() {
    asm volatile("cp.async.commit_group;" ::: "memory");
}
template <int N_> __device__ __forceinline__ void cp_wait() {
    asm volatile("cp.async.wait_group %0;" :: "n"(N_) : "memory");
}

__device__ __forceinline__ uint32_t f2tf32(float x) {
    uint32_t r;
    asm("cvt.rna.tf32.f32 %0, %1;" : "=r"(r) : "f"(x));
    return r;
}

__device__ __forceinline__ void ldsm_x4(uint32_t* r, uint32_t addr) {
    asm volatile("ldmatrix.sync.aligned.m8n8.x4.shared.b16 {%0,%1,%2,%3}, [%4];"
                 : "=r"(r[0]), "=r"(r[1]), "=r"(r[2]), "=r"(r[3]) : "r"(addr));
}

#define MMA_TF32(ACC, A0, A1, A2, A3, B0, B1)                                  \
    asm volatile(                                                              \
        "mma.sync.aligned.m16n8k8.row.col.f32.tf32.tf32.f32 "                  \
        "{%0,%1,%2,%3}, {%4,%5,%6,%7}, {%8,%9}, {%0,%1,%2,%3};"                \
        : "+f"(ACC[0]), "+f"(ACC[1]), "+f"(ACC[2]), "+f"(ACC[3])               \
        : "r"(A0), "r"(A1), "r"(A2), "r"(A3), "r"(B0), "r"(B1))

// ---------------------------------------------------------------------------
// Elementwise split: x -> (hi, lo) tf32 planes.  n4 = n/4.
// ---------------------------------------------------------------------------
__global__ __launch_bounds__(256) void split_kernel(
    const float* __restrict__ in, uint32_t* __restrict__ hi,
    uint32_t* __restrict__ lo, int n4)
{
    int i = blockIdx.x * blockDim.x + threadIdx.x;
    if (i >= n4) return;
    float4 v = ((const float4*)in)[i];
    uint4 h, l;
    h.x = f2tf32(v.x); l.x = f2tf32(v.x - __uint_as_float(h.x));
    h.y = f2tf32(v.y); l.y = f2tf32(v.y - __uint_as_float(h.y));
    h.z = f2tf32(v.z); l.z = f2tf32(v.z - __uint_as_float(h.z));
    h.w = f2tf32(v.w); l.w = f2tf32(v.w - __uint_as_float(h.w));
    ((uint4*)hi)[i] = h;
    ((uint4*)lo)[i] = l;
}

// ---------------------------------------------------------------------------
// 3xTF32 mma.sync GEMM on pre-split hi/lo planes, ldmatrix fragment loads.
//   C[m,n] = sum_k A[m,k]*B[n,k] (+ bias[n]),  ~fp32 accurate
// 256 threads, CTA tile 128x128, BK=32, double-buffered cp.async staging.
// ---------------------------------------------------------------------------
__global__ __launch_bounds__(256) void gemm_3xtf32(
    const uint32_t* __restrict__ Ahi, const uint32_t* __restrict__ Alo,
    const uint32_t* __restrict__ Bhi, const uint32_t* __restrict__ Blo,
    const float* __restrict__ bias, float* __restrict__ C,
    int M, int N, int K)
{
    extern __shared__ uint32_t smem[];        // 2 bufs x 4 planes x 128*SST
    const int BUF = 128 * SST;                // u32 per plane tile
    const uint32_t BUFB = 4u * BUF * 4u;      // bytes per buffer (4 planes)

    const int tid  = threadIdx.x;
    const int wid  = tid >> 5;
    const int lane = tid & 31;
    const int g    = lane >> 2;
    const int t    = lane & 3;
    const int warpM = (wid >> 2) * 64;        // 0 or 64
    const int warpN = (wid & 3) * 32;         // 0,32,64,96
    const int m0 = blockIdx.y * 128;
    const int n0 = blockIdx.x * 128;

    const uint32_t sbase = smem_u32(smem);

    // ldmatrix per-lane base addresses (buffer 0, s=0), in bytes from sbase.
    // A tiles: reg i <- tile i: rows (i&1)*8 + 0..7, col group (i>>1)*4.
    const int aRow = ((lane >> 3) & 1) * 8 + (lane & 7);
    const int aC4  = (lane >> 4) * 4;
    // B x4 covers two n-tiles: reg pairs (tile0,1)=ni0, (tile2,3)=ni0+1.
    const int bNi  = (lane >> 4);             // 0 or 1 -> which n-tile of the pair
    const int bC4  = ((lane >> 3) & 1) * 4;
    const int bRow = lane & 7;

    uint32_t aOffH[4], aOffL[4], bOffH[2], bOffL[2];
    #pragma unroll
    for (int mi = 0; mi < 4; mi++) {
        uint32_t off = (uint32_t)((warpM + mi * 16 + aRow) * SST + aC4) * 4u;
        aOffH[mi] = sbase + off;                       // plane 0 (Ahi)
        aOffL[mi] = sbase + BUF * 4u + off;            // plane 1 (Alo)
    }
    #pragma unroll
    for (int j = 0; j < 2; j++) {
        uint32_t off = (uint32_t)((warpN + (2 * j + bNi) * 8 + bRow) * SST + bC4) * 4u;
        bOffH[j] = sbase + 2u * BUF * 4u + off;        // plane 2 (Bhi)
        bOffL[j] = sbase + 3u * BUF * 4u + off;        // plane 3 (Blo)
    }

    // stage 4 planes of one BK=32 tile into buffer b
    auto load_tile = [&](int kt, int b) {
        const uint32_t dst = sbase + (uint32_t)b * BUFB;
        const uint32_t* gp[4];
        gp[0] = Ahi + (size_t)m0 * K + kt * 32;
        gp[1] = Alo + (size_t)m0 * K + kt * 32;
        gp[2] = Bhi + (size_t)n0 * K + kt * 32;
        gp[3] = Blo + (size_t)n0 * K + kt * 32;
        #pragma unroll
        for (int c = 0; c < 4; c++) {
            int idx = tid + c * 256;          // 0..1023
            int row = idx >> 3, j = idx & 7;
            uint32_t soff = (uint32_t)(row * SST + j * 4) * 4u;
            #pragma unroll
            for (int pl = 0; pl < 4; pl++)
                cp_async16(dst + pl * (BUF * 4u) + soff,
                           gp[pl] + (size_t)row * K + j * 4);
        }
        cp_commit();
    };

    float acc[4][4][4];
    #pragma unroll
    for (int mi = 0; mi < 4; mi++)
        #pragma unroll
        for (int ni = 0; ni < 4; ni++)
            #pragma unroll
            for (int r = 0; r < 4; r++) acc[mi][ni][r] = 0.0f;

    const int ktiles = K / 32;
    load_tile(0, 0);

    for (int kt = 0; kt < ktiles; kt++) {
        const int buf = kt & 1;
        if (kt + 1 < ktiles) { load_tile(kt + 1, buf ^ 1); cp_wait<1>(); }
        else                 { cp_wait<0>(); }
        __syncthreads();

        const uint32_t bo = (uint32_t)buf * BUFB;

        #pragma unroll
        for (int s = 0; s < 4; s++) {
            const uint32_t so = bo + (uint32_t)s * 32u;   // s*8 floats = 32B
            uint32_t ah[4][4], al[4][4], bfh[2][4], bfl[2][4];
            #pragma unroll
            for (int mi = 0; mi < 4; mi++) ldsm_x4(ah[mi], aOffH[mi] + so);
            #pragma unroll
            for (int mi = 0; mi < 4; mi++) ldsm_x4(al[mi], aOffL[mi] + so);
            #pragma unroll
            for (int j = 0; j < 2; j++) ldsm_x4(bfh[j], bOffH[j] + so);
            #pragma unroll
            for (int j = 0; j < 2; j++) ldsm_x4(bfl[j], bOffL[j] + so);

            #pragma unroll
            for (int mi = 0; mi < 4; mi++)
                #pragma unroll
                for (int ni = 0; ni < 4; ni++) {
                    const uint32_t* Bh = &bfh[ni >> 1][(ni & 1) * 2];
                    const uint32_t* Bl = &bfl[ni >> 1][(ni & 1) * 2];
                    MMA_TF32(acc[mi][ni], al[mi][0], al[mi][1], al[mi][2], al[mi][3],
                             Bh[0], Bh[1]);
                    MMA_TF32(acc[mi][ni], ah[mi][0], ah[mi][1], ah[mi][2], ah[mi][3],
                             Bl[0], Bl[1]);
                    MMA_TF32(acc[mi][ni], ah[mi][0], ah[mi][1], ah[mi][2], ah[mi][3],
                             Bh[0], Bh[1]);
                }
        }
        __syncthreads();
    }

    // epilogue
    #pragma unroll
    for (int mi = 0; mi < 4; mi++) {
        const int row = m0 + warpM + mi * 16 + g;
        #pragma unroll
        for (int ni = 0; ni < 4; ni++) {
            const int col = n0 + warpN + ni * 8 + t * 2;
            float bx = 0.f, by = 0.f;
            if (bias) { bx = bias[col]; by = bias[col + 1]; }
            float2 v0 = make_float2(acc[mi][ni][0] + bx, acc[mi][ni][1] + by);
            float2 v1 = make_float2(acc[mi][ni][2] + bx, acc[mi][ni][3] + by);
            *(float2*)(C + (size_t)row * N + col)       = v0;
            *(float2*)(C + (size_t)(row + 8) * N + col) = v1;
        }
    }
}

// ---------------------------------------------------------------------------
// RoPE in-place on q,k of g_qkv.
// ---------------------------------------------------------------------------
__global__ __launch_bounds__(256) void rope_kernel(float* __restrict__ qkv)
{
    int idx = blockIdx.x * blockDim.x + threadIdx.x;
    int d  = idx & 31;
    int h  = (idx >> 5) & 15;
    int p  = (idx >> 9) & 1;
    int nt = idx >> 10;
    int t  = nt & (TT - 1);

    float inv = exp2f(-0.41524101186092029f * (float)d);  // 10000^{-2d/64}
    float fr  = (float)t * inv;
    float c, s;
    sincosf(fr, &s, &c);

    size_t base = ((size_t)nt * 3 + p) * DD + h * HDD + d;
    float x1 = qkv[base];
    float x2 = qkv[base + 32];
    qkv[base]      = x1 * c - x2 * s;
    qkv[base + 32] = x2 * c + x1 * s;
}

// ---------------------------------------------------------------------------
// Banded attention, flash-style online softmax.
// ---------------------------------------------------------------------------
__global__ __launch_bounds__(128) void attn_kernel(
    const float* __restrict__ qkv, float* __restrict__ attn)
{
    const int qt = blockIdx.x;
    const int h  = blockIdx.y;
    const int n  = blockIdx.z;
    const int tq = threadIdx.x;
    const int i  = qt * 128 + tq;
    const int i0 = qt * 128;

    __shared__ float4 Ks[32][16];
    __shared__ float4 Vs[32][16];

    const float* qp = qkv + (((size_t)(n * TT + i) * 3 + 0)) * DD + h * HDD;
    float4 qv[16];
    #pragma unroll
    for (int x = 0; x < 16; x++) qv[x] = ((const float4*)qp)[x];

    float4 acc[16];
    #pragma unroll
    for (int x = 0; x < 16; x++) acc[x] = make_float4(0.f, 0.f, 0.f, 0.f);
    float m = -1e30f, l = 0.0f;

    const int klo = max(0, i0 - WL);
    const int khi = min(TT - 1, i0 + 127 + WR);

    for (int ks = klo; ks <= khi; ks += 32) {
        __syncthreads();
        for (int e = tq; e < 512; e += 128) {
            int row = e >> 4, c4 = e & 15;
            int sg = ks + row;
            float4 kk = make_float4(0.f, 0.f, 0.f, 0.f);
            float4 vv = kk;
            if (sg <= khi) {
                size_t b = ((size_t)(n * TT + sg) * 3) * DD + h * HDD;
                kk = ((const float4*)(qkv + b + DD))[c4];
                vv = ((const float4*)(qkv + b + 2 * DD))[c4];
            }
            Ks[row][c4] = kk;
            Vs[row][c4] = vv;
        }
        __syncthreads();

        const int jmax = min(32, khi - ks + 1);
        for (int j = 0; j < jmax; j++) {
            const int sg = ks + j;
            const bool valid = (sg >= i - WL) && (sg <= i + WR);
            float s = 0.0f;
            #pragma unroll
            for (int x = 0; x < 16; x++) {
                float4 kk = Ks[j][x];
                s = fmaf(qv[x].x, kk.x, s);
                s = fmaf(qv[x].y, kk.y, s);
                s = fmaf(qv[x].z, kk.z, s);
                s = fmaf(qv[x].w, kk.w, s);
            }
            s *= 0.125f;
            if (valid) {
                if (s > m) {
                    float corr = expf(m - s);
                    l *= corr;
                    #pragma unroll
                    for (int x = 0; x < 16; x++) {
                        acc[x].x *= corr; acc[x].y *= corr;
                        acc[x].z *= corr; acc[x].w *= corr;
                    }
                    m = s;
                }
                float p = expf(s - m);
                l += p;
                #pragma unroll
                for (int x = 0; x < 16; x++) {
                    float4 vv = Vs[j][x];
                    acc[x].x = fmaf(p, vv.x, acc[x].x);
                    acc[x].y = fmaf(p, vv.y, acc[x].y);
                    acc[x].z = fmaf(p, vv.z, acc[x].z);
                    acc[x].w = fmaf(p, vv.w, acc[x].w);
                }
            }
        }
    }

    const float inv_l = 1.0f / l;
    float* op = attn + ((size_t)(n * TT + i)) * DD + h * HDD;
    #pragma unroll
    for (int x = 0; x < 16; x++) {
        float4 v = acc[x];
        v.x *= inv_l; v.y *= inv_l; v.z *= inv_l; v.w *= inv_l;
        ((float4*)op)[x] = v;
    }
}

// ---------------------------------------------------------------------------
extern "C" void kernel_launch(void* const* d_in, const int* in_sizes, int n_in,
                              void* d_out, int out_size)
{
    const float* x     = (const float*)d_in[0];
    const float* w_qkv = (const float*)d_in[1];
    const float* w_out = (const float*)d_in[2];
    const float* b_out = (const float*)d_in[3];
    float* out = (float*)d_out;

    float *qkv = nullptr, *attn = nullptr;
    uint32_t *ahi = nullptr, *alo = nullptr, *bhi = nullptr, *blo = nullptr;
    cudaGetSymbolAddress((void**)&qkv,  g_qkv);
    cudaGetSymbolAddress((void**)&attn, g_attn);
    cudaGetSymbolAddress((void**)&ahi,  g_ahi);
    cudaGetSymbolAddress((void**)&alo,  g_alo);
    cudaGetSymbolAddress((void**)&bhi,  g_bhi);
    cudaGetSymbolAddress((void**)&blo,  g_blo);

    const int M = NB * TT;                         // 4096
    const int SMEM_GEMM = 2 * 4 * 128 * SST * 4;   // 147456 bytes

    cudaFuncSetAttribute(gemm_3xtf32, cudaFuncAttributeMaxDynamicSharedMemorySize,
                         SMEM_GEMM);

    // split x and w_qkv into tf32 hi/lo planes
    {
        int n4 = M * DD / 4;
        split_kernel<<<(n4 + 255) / 256, 256>>>(x, ahi, alo, n4);
        n4 = 3 * DD * DD / 4;
        split_kernel<<<(n4 + 255) / 256, 256>>>(w_qkv, bhi, blo, n4);
    }
    // 1) qkv = x @ w_qkv^T
    {
        dim3 grid(3 * DD / 128, M / 128);
        gemm_3xtf32<<<grid, 256, SMEM_GEMM>>>(ahi, alo, bhi, blo, nullptr, qkv,
                                              M, 3 * DD, DD);
    }
    // 2) RoPE
    {
        int total = NB * TT * 2 * HH * 32;
        rope_kernel<<<total / 256, 256>>>(qkv);
    }
    // 3) banded attention
    {
        dim3 grid(TT / 128, HH, NB);
        attn_kernel<<<grid, 128>>>(qkv, attn);
    }
    // split attn and w_out
    {
        int n4 = M * DD / 4;
        split_kernel<<<(n4 + 255) / 256, 256>>>(attn, ahi, alo, n4);
        n4 = DD * DD / 4;
        split_kernel<<<(n4 + 255) / 256, 256>>>(w_out, bhi, blo, n4);
    }
    // 4) out = attn @ w_out^T + b_out
    {
        dim3 grid(DD / 128, M / 128);
        gemm_3xtf32<<<grid, 256, SMEM_GEMM>>>(ahi, alo, bhi, blo, b_out, out,
                                              M, DD, DD);
    }
}

// round 8
// speedup vs baseline: 1.9172x; 1.4720x over previous
#include <cuda_runtime.h>
#include <cuda_bf16.h>
#include <math.h>
#include <stdint.h>

#define NB   2
#define TT   2048
#define DD   1024
#define HH   16
#define HDD  64
#define WL   127
#define WR   128

#define SRB  144   // smem row stride in BYTES for bf16 tiles (BK=64 -> 128B + 16 pad)
#define PLB  18432 // plane bytes: 128 rows * SRB
#define BUFB 73728 // buffer bytes: 4 planes

// Scratch (allocation-free)
__device__ float    g_qkv[(size_t)NB * TT * 3 * DD];
__device__ float    g_attn[(size_t)NB * TT * DD];
__device__ uint16_t g_ahi[(size_t)NB * TT * DD];     // A hi plane (bf16 bits)
__device__ uint16_t g_alo[(size_t)NB * TT * DD];     // A lo plane
__device__ uint16_t g_bhi[(size_t)3 * DD * DD];      // B hi plane
__device__ uint16_t g_blo[(size_t)3 * DD * DD];      // B lo plane

// ---------------------------------------------------------------------------
__device__ __forceinline__ uint32_t smem_u32(const void* p) {
    uint32_t r;
    asm("{ .reg .u64 t; cvta.to.shared.u64 t, %1; cvt.u32.u64 %0, t; }"
        : "=r"(r) : "l"(p));
    return r;
}
__device__ __forceinline__ void cp_async16(uint32_t s, const void* g) {
    asm volatile("cp.async.cg.shared.global [%0], [%1], 16;" :: "r"(s), "l"(g));
}
__device__ __forceinline__ void cp_commit() {
    asm volatile("cp.async.commit_group;" ::: "memory");
}
template <int N_> __device__ __forceinline__ void cp_wait() {
    asm volatile("cp.async.wait_group %0;" :: "n"(N_) : "memory");
}
__device__ __forceinline__ void ldsm_x4(uint32_t* r, uint32_t addr) {
    asm volatile("ldmatrix.sync.aligned.m8n8.x4.shared.b16 {%0,%1,%2,%3}, [%4];"
                 : "=r"(r[0]), "=r"(r[1]), "=r"(r[2]), "=r"(r[3]) : "r"(addr));
}

__device__ __forceinline__ uint16_t f2bf(float x) {
    return __bfloat16_as_ushort(__float2bfloat16_rn(x));
}

#define MMA_BF16(ACC, A, B0, B1)                                               \
    asm volatile(                                                              \
        "mma.sync.aligned.m16n8k16.row.col.f32.bf16.bf16.f32 "                 \
        "{%0,%1,%2,%3}, {%4,%5,%6,%7}, {%8,%9}, {%0,%1,%2,%3};"                \
        : "+f"(ACC[0]), "+f"(ACC[1]), "+f"(ACC[2]), "+f"(ACC[3])               \
        : "r"((A)[0]), "r"((A)[1]), "r"((A)[2]), "r"((A)[3]), "r"(B0), "r"(B1))

// ---------------------------------------------------------------------------
// Elementwise split: x -> (hi, lo) bf16 planes.  n4 = n/4.
// ---------------------------------------------------------------------------
__global__ __launch_bounds__(256) void split_kernel(
    const float* __restrict__ in, uint16_t* __restrict__ hi,
    uint16_t* __restrict__ lo, int n4)
{
    int i = blockIdx.x * blockDim.x + threadIdx.x;
    if (i >= n4) return;
    float4 v = ((const float4*)in)[i];
    ushort4 h, l;
    h.x = f2bf(v.x); l.x = f2bf(v.x - __bfloat162float(__ushort_as_bfloat16(h.x)));
    h.y = f2bf(v.y); l.y = f2bf(v.y - __bfloat162float(__ushort_as_bfloat16(h.y)));
    h.z = f2bf(v.z); l.z = f2bf(v.z - __bfloat162float(__ushort_as_bfloat16(h.z)));
    h.w = f2bf(v.w); l.w = f2bf(v.w - __bfloat162float(__ushort_as_bfloat16(h.w)));
    ((ushort4*)hi)[i] = h;
    ((ushort4*)lo)[i] = l;
}

// ---------------------------------------------------------------------------
// 3-term bf16 mma GEMM on pre-split hi/lo planes (~17-bit effective mantissa):
//   C[m,n] = sum_k A[m,k]*B[n,k] (+ bias[n])
// Planes: [M,K]/[N,K] row-major bf16 bits. M%128==0, N%128==0, K%64==0.
// 256 threads, CTA tile 128x128, BK=64, double-buffered cp.async staging.
// ---------------------------------------------------------------------------
__global__ __launch_bounds__(256) void gemm_3xbf16(
    const uint16_t* __restrict__ Ahi, const uint16_t* __restrict__ Alo,
    const uint16_t* __restrict__ Bhi, const uint16_t* __restrict__ Blo,
    const float* __restrict__ bias, float* __restrict__ C,
    int M, int N, int K)
{
    extern __shared__ char smem[];            // 2 bufs x 4 planes x PLB
    const int tid  = threadIdx.x;
    const int wid  = tid >> 5;
    const int lane = tid & 31;
    const int g    = lane >> 2;
    const int t    = lane & 3;
    const int warpM = (wid >> 2) * 64;        // 0 or 64
    const int warpN = (wid & 3) * 32;         // 0,32,64,96
    const int m0 = blockIdx.y * 128;
    const int n0 = blockIdx.x * 128;

    const uint32_t sbase = smem_u32(smem);

    // ldmatrix per-lane addresses (buffer 0, k-step 0), bytes from sbase.
    // A m16k16 frag: lanes0-7 rows0-7 kb0 | 8-15 rows8-15 kb0 | 16-23 rows0-7 kb16 | 24-31 rows8-15 kb16
    const int aRow = ((lane >> 3) & 1) * 8 + (lane & 7);
    const int aKb  = (lane >> 4) * 16;
    // B pair-of-n-tiles frag: lanes0-7 nrows0-7 kb0 | 8-15 nrows0-7 kb16 | 16-23 nrows8-15 kb0 | 24-31 nrows8-15 kb16
    const int bRow = ((lane >> 4) & 1) * 8 + (lane & 7);
    const int bKb  = ((lane >> 3) & 1) * 16;

    uint32_t aOffH[4], aOffL[4], bOffH[2], bOffL[2];
    #pragma unroll
    for (int mi = 0; mi < 4; mi++) {
        uint32_t off = (uint32_t)((warpM + mi * 16 + aRow) * SRB + aKb);
        aOffH[mi] = sbase + off;
        aOffL[mi] = sbase + PLB + off;
    }
    #pragma unroll
    for (int j = 0; j < 2; j++) {
        uint32_t off = (uint32_t)((warpN + j * 16 + bRow) * SRB + bKb);
        bOffH[j] = sbase + 2u * PLB + off;
        bOffL[j] = sbase + 3u * PLB + off;
    }

    // stage 4 planes of one BK=64 tile into buffer b
    auto load_tile = [&](int kt, int b) {
        const uint32_t dst = sbase + (uint32_t)b * BUFB;
        const uint16_t* gp[4];
        gp[0] = Ahi + (size_t)m0 * K + kt * 64;
        gp[1] = Alo + (size_t)m0 * K + kt * 64;
        gp[2] = Bhi + (size_t)n0 * K + kt * 64;
        gp[3] = Blo + (size_t)n0 * K + kt * 64;
        #pragma unroll
        for (int c = 0; c < 4; c++) {
            int idx = tid + c * 256;          // 0..1023
            int row = idx >> 3, j = idx & 7;  // 8 x 16B chunks per 128B row
            uint32_t soff = (uint32_t)(row * SRB + j * 16);
            #pragma unroll
            for (int pl = 0; pl < 4; pl++)
                cp_async16(dst + pl * (uint32_t)PLB + soff,
                           gp[pl] + (size_t)row * K + j * 8);
        }
        cp_commit();
    };

    float acc[4][4][4];
    #pragma unroll
    for (int mi = 0; mi < 4; mi++)
        #pragma unroll
        for (int ni = 0; ni < 4; ni++)
            #pragma unroll
            for (int r = 0; r < 4; r++) acc[mi][ni][r] = 0.0f;

    const int ktiles = K / 64;
    load_tile(0, 0);

    for (int kt = 0; kt < ktiles; kt++) {
        const int buf = kt & 1;
        if (kt + 1 < ktiles) { load_tile(kt + 1, buf ^ 1); cp_wait<1>(); }
        else                 { cp_wait<0>(); }
        __syncthreads();

        const uint32_t bo = (uint32_t)buf * BUFB;

        #pragma unroll
        for (int s = 0; s < 4; s++) {         // 4 k16-steps in BK=64
            const uint32_t so = bo + (uint32_t)s * 32u;   // 16 bf16 = 32B
            uint32_t ah[4][4], al[4][4], bfh[2][4], bfl[2][4];
            #pragma unroll
            for (int mi = 0; mi < 4; mi++) ldsm_x4(ah[mi], aOffH[mi] + so);
            #pragma unroll
            for (int mi = 0; mi < 4; mi++) ldsm_x4(al[mi], aOffL[mi] + so);
            #pragma unroll
            for (int j = 0; j < 2; j++) ldsm_x4(bfh[j], bOffH[j] + so);
            #pragma unroll
            for (int j = 0; j < 2; j++) ldsm_x4(bfl[j], bOffL[j] + so);

            #pragma unroll
            for (int mi = 0; mi < 4; mi++)
                #pragma unroll
                for (int ni = 0; ni < 4; ni++) {
                    const uint32_t* Bh = &bfh[ni >> 1][(ni & 1) * 2];
                    const uint32_t* Bl = &bfl[ni >> 1][(ni & 1) * 2];
                    MMA_BF16(acc[mi][ni], al[mi], Bh[0], Bh[1]);
                    MMA_BF16(acc[mi][ni], ah[mi], Bl[0], Bl[1]);
                    MMA_BF16(acc[mi][ni], ah[mi], Bh[0], Bh[1]);
                }
        }
        __syncthreads();
    }

    // epilogue
    #pragma unroll
    for (int mi = 0; mi < 4; mi++) {
        const int row = m0 + warpM + mi * 16 + g;
        #pragma unroll
        for (int ni = 0; ni < 4; ni++) {
            const int col = n0 + warpN + ni * 8 + t * 2;
            float bx = 0.f, by = 0.f;
            if (bias) { bx = bias[col]; by = bias[col + 1]; }
            float2 v0 = make_float2(acc[mi][ni][0] + bx, acc[mi][ni][1] + by);
            float2 v1 = make_float2(acc[mi][ni][2] + bx, acc[mi][ni][3] + by);
            *(float2*)(C + (size_t)row * N + col)       = v0;
            *(float2*)(C + (size_t)(row + 8) * N + col) = v1;
        }
    }
}

// ---------------------------------------------------------------------------
// RoPE in-place on q,k of g_qkv.
// ---------------------------------------------------------------------------
__global__ __launch_bounds__(256) void rope_kernel(float* __restrict__ qkv)
{
    int idx = blockIdx.x * blockDim.x + threadIdx.x;
    int d  = idx & 31;
    int h  = (idx >> 5) & 15;
    int p  = (idx >> 9) & 1;
    int nt = idx >> 10;
    int t  = nt & (TT - 1);

    float inv = exp2f(-0.41524101186092029f * (float)d);  // 10000^{-2d/64}
    float fr  = (float)t * inv;
    float c, s;
    sincosf(fr, &s, &c);

    size_t base = ((size_t)nt * 3 + p) * DD + h * HDD + d;
    float x1 = qkv[base];
    float x2 = qkv[base + 32];
    qkv[base]      = x1 * c - x2 * s;
    qkv[base + 32] = x2 * c + x1 * s;
}

// ---------------------------------------------------------------------------
// Banded attention, flash-style online softmax.
// ---------------------------------------------------------------------------
__global__ __launch_bounds__(128) void attn_kernel(
    const float* __restrict__ qkv, float* __restrict__ attn)
{
    const int qt = blockIdx.x;
    const int h  = blockIdx.y;
    const int n  = blockIdx.z;
    const int tq = threadIdx.x;
    const int i  = qt * 128 + tq;
    const int i0 = qt * 128;

    __shared__ float4 Ks[32][16];
    __shared__ float4 Vs[32][16];

    const float* qp = qkv + (((size_t)(n * TT + i) * 3 + 0)) * DD + h * HDD;
    float4 qv[16];
    #pragma unroll
    for (int x = 0; x < 16; x++) qv[x] = ((const float4*)qp)[x];

    float4 acc[16];
    #pragma unroll
    for (int x = 0; x < 16; x++) acc[x] = make_float4(0.f, 0.f, 0.f, 0.f);
    float m = -1e30f, l = 0.0f;

    const int klo = max(0, i0 - WL);
    const int khi = min(TT - 1, i0 + 127 + WR);

    for (int ks = klo; ks <= khi; ks += 32) {
        __syncthreads();
        for (int e = tq; e < 512; e += 128) {
            int row = e >> 4, c4 = e & 15;
            int sg = ks + row;
            float4 kk = make_float4(0.f, 0.f, 0.f, 0.f);
            float4 vv = kk;
            if (sg <= khi) {
                size_t b = ((size_t)(n * TT + sg) * 3) * DD + h * HDD;
                kk = ((const float4*)(qkv + b + DD))[c4];
                vv = ((const float4*)(qkv + b + 2 * DD))[c4];
            }
            Ks[row][c4] = kk;
            Vs[row][c4] = vv;
        }
        __syncthreads();

        const int jmax = min(32, khi - ks + 1);
        for (int j = 0; j < jmax; j++) {
            const int sg = ks + j;
            const bool valid = (sg >= i - WL) && (sg <= i + WR);
            float s = 0.0f;
            #pragma unroll
            for (int x = 0; x < 16; x++) {
                float4 kk = Ks[j][x];
                s = fmaf(qv[x].x, kk.x, s);
                s = fmaf(qv[x].y, kk.y, s);
                s = fmaf(qv[x].z, kk.z, s);
                s = fmaf(qv[x].w, kk.w, s);
            }
            s *= 0.125f;
            if (valid) {
                if (s > m) {
                    float corr = expf(m - s);
                    l *= corr;
                    #pragma unroll
                    for (int x = 0; x < 16; x++) {
                        acc[x].x *= corr; acc[x].y *= corr;
                        acc[x].z *= corr; acc[x].w *= corr;
                    }
                    m = s;
                }
                float p = expf(s - m);
                l += p;
                #pragma unroll
                for (int x = 0; x < 16; x++) {
                    float4 vv = Vs[j][x];
                    acc[x].x = fmaf(p, vv.x, acc[x].x);
                    acc[x].y = fmaf(p, vv.y, acc[x].y);
                    acc[x].z = fmaf(p, vv.z, acc[x].z);
                    acc[x].w = fmaf(p, vv.w, acc[x].w);
                }
            }
        }
    }

    const float inv_l = 1.0f / l;
    float* op = attn + ((size_t)(n * TT + i)) * DD + h * HDD;
    #pragma unroll
    for (int x = 0; x < 16; x++) {
        float4 v = acc[x];
        v.x *= inv_l; v.y *= inv_l; v.z *= inv_l; v.w *= inv_l;
        ((float4*)op)[x] = v;
    }
}

// ---------------------------------------------------------------------------
extern "C" void kernel_launch(void* const* d_in, const int* in_sizes, int n_in,
                              void* d_out, int out_size)
{
    const float* x     = (const float*)d_in[0];
    const float* w_qkv = (const float*)d_in[1];
    const float* w_out = (const float*)d_in[2];
    const float* b_out = (const float*)d_in[3];
    float* out = (float*)d_out;

    float *qkv = nullptr, *attn = nullptr;
    uint16_t *ahi = nullptr, *alo = nullptr, *bhi = nullptr, *blo = nullptr;
    cudaGetSymbolAddress((void**)&qkv,  g_qkv);
    cudaGetSymbolAddress((void**)&attn, g_attn);
    cudaGetSymbolAddress((void**)&ahi,  g_ahi);
    cudaGetSymbolAddress((void**)&alo,  g_alo);
    cudaGetSymbolAddress((void**)&bhi,  g_bhi);
    cudaGetSymbolAddress((void**)&blo,  g_blo);

    const int M = NB * TT;                 // 4096
    const int SMEM_GEMM = 2 * BUFB;        // 147456 bytes

    cudaFuncSetAttribute(gemm_3xbf16, cudaFuncAttributeMaxDynamicSharedMemorySize,
                         SMEM_GEMM);

    // split x and w_qkv into bf16 hi/lo planes
    {
        int n4 = M * DD / 4;
        split_kernel<<<(n4 + 255) / 256, 256>>>(x, ahi, alo, n4);
        n4 = 3 * DD * DD / 4;
        split_kernel<<<(n4 + 255) / 256, 256>>>(w_qkv, bhi, blo, n4);
    }
    // 1) qkv = x @ w_qkv^T
    {
        dim3 grid(3 * DD / 128, M / 128);
        gemm_3xbf16<<<grid, 256, SMEM_GEMM>>>(ahi, alo, bhi, blo, nullptr, qkv,
                                              M, 3 * DD, DD);
    }
    // 2) RoPE
    {
        int total = NB * TT * 2 * HH * 32;
        rope_kernel<<<total / 256, 256>>>(qkv);
    }
    // 3) banded attention
    {
        dim3 grid(TT / 128, HH, NB);
        attn_kernel<<<grid, 128>>>(qkv, attn);
    }
    // split attn and w_out
    {
        int n4 = M * DD / 4;
        split_kernel<<<(n4 + 255) / 256, 256>>>(attn, ahi, alo, n4);
        n4 = DD * DD / 4;
        split_kernel<<<(n4 + 255) / 256, 256>>>(w_out, bhi, blo, n4);
    }
    // 4) out = attn @ w_out^T + b_out
    {
        dim3 grid(DD / 128, M / 128);
        gemm_3xbf16<<<grid, 256, SMEM_GEMM>>>(ahi, alo, bhi, blo, b_out, out,
                                              M, DD, DD);
    }
}

// round 10
// speedup vs baseline: 2.9708x; 1.5495x over previous
#include <cuda_runtime.h>
#include <cuda_bf16.h>
#include <math.h>
#include <stdint.h>

#define NB   2
#define TT   2048
#define DD   1024
#define HH   16
#define HDD  64
#define WL   127
#define WR   128

#define SRB  144   // smem row stride in BYTES for bf16 tiles
#define PLB  18432 // GEMM plane bytes: 128 rows * SRB
#define BUFB 73728 // GEMM buffer bytes: 4 planes
#define APLB 9216  // attn plane bytes: 64 rows * SRB

// Scratch (allocation-free)
__device__ float    g_qkv[(size_t)NB * TT * 3 * DD];
__device__ uint16_t g_ahi[(size_t)NB * TT * DD];     // GEMM A hi plane
__device__ uint16_t g_alo[(size_t)NB * TT * DD];     // GEMM A lo plane
__device__ uint16_t g_bhi[(size_t)3 * DD * DD];      // GEMM B hi plane
__device__ uint16_t g_blo[(size_t)3 * DD * DD];      // GEMM B lo plane
// attention planes [n,h,t,64] (Q,K) and [n,h,64,t] (V^T)
#define APL ((size_t)NB * HH * TT * HDD)
__device__ uint16_t g_qh[APL], g_ql[APL];
__device__ uint16_t g_kh[APL], g_kl[APL];
__device__ uint16_t g_vth[APL], g_vtl[APL];

// ---------------------------------------------------------------------------
__device__ __forceinline__ uint32_t smem_u32(const void* p) {
    uint32_t r;
    asm("{ .reg .u64 t; cvta.to.shared.u64 t, %1; cvt.u32.u64 %0, t; }"
        : "=r"(r) : "l"(p));
    return r;
}
__device__ __forceinline__ void cp_async16(uint32_t s, const void* g) {
    asm volatile("cp.async.cg.shared.global [%0], [%1], 16;" :: "r"(s), "l"(g));
}
__device__ __forceinline__ void cp_commit() {
    asm volatile("cp.async.commit_group;" ::: "memory");
}
template <int N_> __device__ __forceinline__ void cp_wait() {
    asm volatile("cp.async.wait_group %0;" :: "n"(N_) : "memory");
}
__device__ __forceinline__ void ldsm_x4(uint32_t* r, uint32_t addr) {
    asm volatile("ldmatrix.sync.aligned.m8n8.x4.shared.b16 {%0,%1,%2,%3}, [%4];"
                 : "=r"(r[0]), "=r"(r[1]), "=r"(r[2]), "=r"(r[3]) : "r"(addr));
}
__device__ __forceinline__ uint16_t f2bf(float x) {
    return __bfloat16_as_ushort(__float2bfloat16_rn(x));
}
// split a into hi bf16, residual lo bf16; returns hi bits, writes lo bits
__device__ __forceinline__ uint32_t pack_hi_lo(float a, float b, uint32_t& lo) {
    uint16_t ha = f2bf(a), hb = f2bf(b);
    float ra = a - __uint_as_float((uint32_t)ha << 16);
    float rb = b - __uint_as_float((uint32_t)hb << 16);
    lo = (uint32_t)f2bf(ra) | ((uint32_t)f2bf(rb) << 16);
    return (uint32_t)ha | ((uint32_t)hb << 16);
}

#define MMA_BF16(ACC, A, B0, B1)                                               \
    asm volatile(                                                              \
        "mma.sync.aligned.m16n8k16.row.col.f32.bf16.bf16.f32 "                 \
        "{%0,%1,%2,%3}, {%4,%5,%6,%7}, {%8,%9}, {%0,%1,%2,%3};"                \
        : "+f"(ACC[0]), "+f"(ACC[1]), "+f"(ACC[2]), "+f"(ACC[3])               \
        : "r"((A)[0]), "r"((A)[1]), "r"((A)[2]), "r"((A)[3]), "r"(B0), "r"(B1))

// ---------------------------------------------------------------------------
// Elementwise split: x -> (hi, lo) bf16 planes.  n4 = n/4.
// ---------------------------------------------------------------------------
__global__ __launch_bounds__(256) void split_kernel(
    const float* __restrict__ in, uint16_t* __restrict__ hi,
    uint16_t* __restrict__ lo, int n4)
{
    int i = blockIdx.x * blockDim.x + threadIdx.x;
    if (i >= n4) return;
    float4 v = ((const float4*)in)[i];
    ushort4 h, l;
    h.x = f2bf(v.x); l.x = f2bf(v.x - __uint_as_float((uint32_t)h.x << 16));
    h.y = f2bf(v.y); l.y = f2bf(v.y - __uint_as_float((uint32_t)h.y << 16));
    h.z = f2bf(v.z); l.z = f2bf(v.z - __uint_as_float((uint32_t)h.z << 16));
    h.w = f2bf(v.w); l.w = f2bf(v.w - __uint_as_float((uint32_t)h.w << 16));
    ((ushort4*)hi)[i] = h;
    ((ushort4*)lo)[i] = l;
}

// ---------------------------------------------------------------------------
// 3-term bf16 mma GEMM (unchanged from R8).
// ---------------------------------------------------------------------------
__global__ __launch_bounds__(256) void gemm_3xbf16(
    const uint16_t* __restrict__ Ahi, const uint16_t* __restrict__ Alo,
    const uint16_t* __restrict__ Bhi, const uint16_t* __restrict__ Blo,
    const float* __restrict__ bias, float* __restrict__ C,
    int M, int N, int K)
{
    extern __shared__ char smem[];
    const int tid  = threadIdx.x;
    const int wid  = tid >> 5;
    const int lane = tid & 31;
    const int g    = lane >> 2;
    const int t    = lane & 3;
    const int warpM = (wid >> 2) * 64;
    const int warpN = (wid & 3) * 32;
    const int m0 = blockIdx.y * 128;
    const int n0 = blockIdx.x * 128;

    const uint32_t sbase = smem_u32(smem);

    const int aRow = ((lane >> 3) & 1) * 8 + (lane & 7);
    const int aKb  = (lane >> 4) * 16;
    const int bRow = ((lane >> 4) & 1) * 8 + (lane & 7);
    const int bKb  = ((lane >> 3) & 1) * 16;

    uint32_t aOffH[4], aOffL[4], bOffH[2], bOffL[2];
    #pragma unroll
    for (int mi = 0; mi < 4; mi++) {
        uint32_t off = (uint32_t)((warpM + mi * 16 + aRow) * SRB + aKb);
        aOffH[mi] = sbase + off;
        aOffL[mi] = sbase + PLB + off;
    }
    #pragma unroll
    for (int j = 0; j < 2; j++) {
        uint32_t off = (uint32_t)((warpN + j * 16 + bRow) * SRB + bKb);
        bOffH[j] = sbase + 2u * PLB + off;
        bOffL[j] = sbase + 3u * PLB + off;
    }

    auto load_tile = [&](int kt, int b) {
        const uint32_t dst = sbase + (uint32_t)b * BUFB;
        const uint16_t* gp[4];
        gp[0] = Ahi + (size_t)m0 * K + kt * 64;
        gp[1] = Alo + (size_t)m0 * K + kt * 64;
        gp[2] = Bhi + (size_t)n0 * K + kt * 64;
        gp[3] = Blo + (size_t)n0 * K + kt * 64;
        #pragma unroll
        for (int c = 0; c < 4; c++) {
            int idx = tid + c * 256;
            int row = idx >> 3, j = idx & 7;
            uint32_t soff = (uint32_t)(row * SRB + j * 16);
            #pragma unroll
            for (int pl = 0; pl < 4; pl++)
                cp_async16(dst + pl * (uint32_t)PLB + soff,
                           gp[pl] + (size_t)row * K + j * 8);
        }
        cp_commit();
    };

    float acc[4][4][4];
    #pragma unroll
    for (int mi = 0; mi < 4; mi++)
        #pragma unroll
        for (int ni = 0; ni < 4; ni++)
            #pragma unroll
            for (int r = 0; r < 4; r++) acc[mi][ni][r] = 0.0f;

    const int ktiles = K / 64;
    load_tile(0, 0);

    for (int kt = 0; kt < ktiles; kt++) {
        const int buf = kt & 1;
        if (kt + 1 < ktiles) { load_tile(kt + 1, buf ^ 1); cp_wait<1>(); }
        else                 { cp_wait<0>(); }
        __syncthreads();

        const uint32_t bo = (uint32_t)buf * BUFB;

        #pragma unroll
        for (int s = 0; s < 4; s++) {
            const uint32_t so = bo + (uint32_t)s * 32u;
            uint32_t ah[4][4], al[4][4], bfh[2][4], bfl[2][4];
            #pragma unroll
            for (int mi = 0; mi < 4; mi++) ldsm_x4(ah[mi], aOffH[mi] + so);
            #pragma unroll
            for (int mi = 0; mi < 4; mi++) ldsm_x4(al[mi], aOffL[mi] + so);
            #pragma unroll
            for (int j = 0; j < 2; j++) ldsm_x4(bfh[j], bOffH[j] + so);
            #pragma unroll
            for (int j = 0; j < 2; j++) ldsm_x4(bfl[j], bOffL[j] + so);

            #pragma unroll
            for (int mi = 0; mi < 4; mi++)
                #pragma unroll
                for (int ni = 0; ni < 4; ni++) {
                    const uint32_t* Bh = &bfh[ni >> 1][(ni & 1) * 2];
                    const uint32_t* Bl = &bfl[ni >> 1][(ni & 1) * 2];
                    MMA_BF16(acc[mi][ni], al[mi], Bh[0], Bh[1]);
                    MMA_BF16(acc[mi][ni], ah[mi], Bl[0], Bl[1]);
                    MMA_BF16(acc[mi][ni], ah[mi], Bh[0], Bh[1]);
                }
        }
        __syncthreads();
    }

    #pragma unroll
    for (int mi = 0; mi < 4; mi++) {
        const int row = m0 + warpM + mi * 16 + g;
        #pragma unroll
        for (int ni = 0; ni < 4; ni++) {
            const int col = n0 + warpN + ni * 8 + t * 2;
            float bx = 0.f, by = 0.f;
            if (bias) { bx = bias[col]; by = bias[col + 1]; }
            float2 v0 = make_float2(acc[mi][ni][0] + bx, acc[mi][ni][1] + by);
            float2 v1 = make_float2(acc[mi][ni][2] + bx, acc[mi][ni][3] + by);
            *(float2*)(C + (size_t)row * N + col)       = v0;
            *(float2*)(C + (size_t)(row + 8) * N + col) = v1;
        }
    }
}

// ---------------------------------------------------------------------------
// RoPE + bf16 hi/lo split of q (scaled by 1/8) and k into [n,h,t,64] planes.
// ---------------------------------------------------------------------------
__global__ __launch_bounds__(256) void rope_split(
    const float* __restrict__ qkv,
    uint16_t* __restrict__ qh, uint16_t* __restrict__ ql,
    uint16_t* __restrict__ kh, uint16_t* __restrict__ kl)
{
    int idx = blockIdx.x * blockDim.x + threadIdx.x;
    int d  = idx & 31;
    int h  = (idx >> 5) & 15;
    int p  = (idx >> 9) & 1;
    int nt = idx >> 10;
    int t  = nt & (TT - 1);
    int n  = nt >> 11;

    float inv = exp2f(-0.41524101186092029f * (float)d);
    float fr  = (float)t * inv;
    float c, s;
    sincosf(fr, &s, &c);

    size_t base = ((size_t)nt * 3 + p) * DD + h * HDD + d;
    float x1 = qkv[base];
    float x2 = qkv[base + 32];
    float y1 = x1 * c - x2 * s;
    float y2 = x2 * c + x1 * s;
    if (p == 0) { y1 *= 0.125f; y2 *= 0.125f; }   // fold 1/sqrt(64) into Q

    uint16_t* H = p ? kh : qh;
    uint16_t* L = p ? kl : ql;
    size_t dst = ((size_t)((n * HH + h) * TT) + t) * HDD + d;
    uint16_t h1 = f2bf(y1);
    uint16_t h2 = f2bf(y2);
    H[dst]      = h1;
    H[dst + 32] = h2;
    L[dst]      = f2bf(y1 - __uint_as_float((uint32_t)h1 << 16));
    L[dst + 32] = f2bf(y2 - __uint_as_float((uint32_t)h2 << 16));
}

// ---------------------------------------------------------------------------
// V transpose + split: qkv v part [t][h,d] -> planes [n,h,d,t] hi/lo.
// Block: (ttile of 64, h, n), 256 threads.
// ---------------------------------------------------------------------------
__global__ __launch_bounds__(256) void vtrans_split(
    const float* __restrict__ qkv,
    uint16_t* __restrict__ vh, uint16_t* __restrict__ vl)
{
    __shared__ float vs[64 * 65];
    const int t0 = blockIdx.x * 64;
    const int h  = blockIdx.y;
    const int n  = blockIdx.z;
    const int tid = threadIdx.x;

    for (int e = tid; e < 4096; e += 256) {
        int tr = e >> 6, d = e & 63;
        float v = qkv[(((size_t)(n * TT + t0 + tr) * 3) + 2) * DD + h * HDD + d];
        vs[d * 65 + tr] = v;
    }
    __syncthreads();
    for (int e = tid; e < 4096; e += 256) {
        int d = e >> 6, tc = e & 63;
        float v = vs[d * 65 + tc];
        uint16_t hb = f2bf(v);
        size_t dst = ((size_t)((n * HH + h) * HDD) + d) * TT + t0 + tc;
        vh[dst] = hb;
        vl[dst] = f2bf(v - __uint_as_float((uint32_t)hb << 16));
    }
}

// ---------------------------------------------------------------------------
// Flash attention, 3-term bf16 mma. Block = (qtile 64, head, batch), 128 thr.
// Writes O directly as bf16 hi/lo planes (GEMM2 A operand).
// ---------------------------------------------------------------------------
__global__ __launch_bounds__(128) void attn_mma(
    const uint16_t* __restrict__ Qh, const uint16_t* __restrict__ Ql,
    const uint16_t* __restrict__ Kh, const uint16_t* __restrict__ Kl,
    const uint16_t* __restrict__ Vh, const uint16_t* __restrict__ Vl,
    uint16_t* __restrict__ Oh, uint16_t* __restrict__ Ol)
{
    __shared__ char smem[4 * APLB];
    const uint32_t sb = smem_u32(smem);
    const uint32_t sKh = sb, sKl = sb + APLB, sVh = sb + 2 * APLB, sVl = sb + 3 * APLB;

    const int q0 = blockIdx.x * 64;
    const int h  = blockIdx.y;
    const int n  = blockIdx.z;
    const int tid = threadIdx.x;
    const int wid = tid >> 5;
    const int lane = tid & 31;
    const int g = lane >> 2;
    const int t = lane & 3;

    const size_t headoff  = (size_t)(n * HH + h) * TT * HDD;   // [t][d] planes
    const size_t vheadoff = (size_t)(n * HH + h) * HDD * TT;   // [d][t] planes

    const int aRow = ((lane >> 3) & 1) * 8 + (lane & 7);
    const int aKb  = (lane >> 4) * 16;
    const int bRow = ((lane >> 4) & 1) * 8 + (lane & 7);
    const int bKb  = ((lane >> 3) & 1) * 16;

    // ---- stage Q tile into sKh/sKl, load fragments ----
    {
        #pragma unroll
        for (int c = 0; c < 4; c++) {
            int idx = tid + c * 128;
            int row = idx >> 3, j = idx & 7;
            uint32_t soff = (uint32_t)(row * SRB + j * 16);
            cp_async16(sKh + soff, Qh + headoff + (size_t)(q0 + row) * HDD + j * 8);
            cp_async16(sKl + soff, Ql + headoff + (size_t)(q0 + row) * HDD + j * 8);
        }
        cp_commit(); cp_wait<0>();
        __syncthreads();
    }
    uint32_t qfh[4][4], qfl[4][4];
    #pragma unroll
    for (int s = 0; s < 4; s++) {
        uint32_t off = (uint32_t)((wid * 16 + aRow) * SRB + aKb + s * 32);
        ldsm_x4(qfh[s], sKh + off);
        ldsm_x4(qfl[s], sKl + off);
    }
    __syncthreads();

    float O[8][4];
    #pragma unroll
    for (int nd = 0; nd < 8; nd++)
        #pragma unroll
        for (int c = 0; c < 4; c++) O[nd][c] = 0.0f;
    float m0 = -1e30f, m1 = -1e30f, l0 = 0.0f, l1 = 0.0f;

    const int klo = max(0, q0 - WL);
    const int khi = min(TT - 1, q0 + 63 + WR);
    const int i0  = q0 + wid * 16 + g;      // row for c0,c1; +8 for c2,c3

    for (int kt = klo & ~63; kt <= khi; kt += 64) {
        // ---- load K,V tiles ----
        #pragma unroll
        for (int c = 0; c < 4; c++) {
            int idx = tid + c * 128;
            int row = idx >> 3, j = idx & 7;
            uint32_t soff = (uint32_t)(row * SRB + j * 16);
            cp_async16(sKh + soff, Kh + headoff + (size_t)(kt + row) * HDD + j * 8);
            cp_async16(sKl + soff, Kl + headoff + (size_t)(kt + row) * HDD + j * 8);
            cp_async16(sVh + soff, Vh + vheadoff + (size_t)row * TT + kt + j * 8);
            cp_async16(sVl + soff, Vl + vheadoff + (size_t)row * TT + kt + j * 8);
        }
        cp_commit(); cp_wait<0>();
        __syncthreads();

        // ---- S = Q K^T (scale pre-folded into Q) ----
        float S[8][4];
        #pragma unroll
        for (int nt = 0; nt < 8; nt++)
            #pragma unroll
            for (int c = 0; c < 4; c++) S[nt][c] = 0.0f;

        #pragma unroll
        for (int s = 0; s < 4; s++) {
            uint32_t kbh[4][4], kbl[4][4];
            #pragma unroll
            for (int j = 0; j < 4; j++) {
                uint32_t off = (uint32_t)((j * 16 + bRow) * SRB + bKb + s * 32);
                ldsm_x4(kbh[j], sKh + off);
                ldsm_x4(kbl[j], sKl + off);
            }
            #pragma unroll
            for (int nt = 0; nt < 8; nt++) {
                const uint32_t* Bh = &kbh[nt >> 1][(nt & 1) * 2];
                const uint32_t* Bl = &kbl[nt >> 1][(nt & 1) * 2];
                MMA_BF16(S[nt], qfl[s], Bh[0], Bh[1]);
                MMA_BF16(S[nt], qfh[s], Bl[0], Bl[1]);
                MMA_BF16(S[nt], qfh[s], Bh[0], Bh[1]);
            }
        }

        // ---- band mask (edge tiles only) ----
        if (kt < q0 - 64 || kt > q0 + 64) {
            #pragma unroll
            for (int nt = 0; nt < 8; nt++)
                #pragma unroll
                for (int c = 0; c < 4; c++) {
                    int j = kt + nt * 8 + 2 * t + (c & 1);
                    int i = i0 + ((c >> 1) << 3);
                    if (j < i - WL || j > i + WR) S[nt][c] = -1e30f;
                }
        }

        // ---- online softmax ----
        float mx0 = -1e30f, mx1 = -1e30f;
        #pragma unroll
        for (int nt = 0; nt < 8; nt++) {
            mx0 = fmaxf(mx0, fmaxf(S[nt][0], S[nt][1]));
            mx1 = fmaxf(mx1, fmaxf(S[nt][2], S[nt][3]));
        }
        mx0 = fmaxf(mx0, __shfl_xor_sync(0xffffffffu, mx0, 1));
        mx0 = fmaxf(mx0, __shfl_xor_sync(0xffffffffu, mx0, 2));
        mx1 = fmaxf(mx1, __shfl_xor_sync(0xffffffffu, mx1, 1));
        mx1 = fmaxf(mx1, __shfl_xor_sync(0xffffffffu, mx1, 2));

        float mn0 = fmaxf(m0, mx0), mn1 = fmaxf(m1, mx1);
        float cr0 = __expf(m0 - mn0), cr1 = __expf(m1 - mn1);
        float mc0 = fmaxf(mn0, -1e29f), mc1 = fmaxf(mn1, -1e29f);

        float sum0 = 0.0f, sum1 = 0.0f;
        #pragma unroll
        for (int nt = 0; nt < 8; nt++) {
            S[nt][0] = __expf(S[nt][0] - mc0);
            S[nt][1] = __expf(S[nt][1] - mc0);
            S[nt][2] = __expf(S[nt][2] - mc1);
            S[nt][3] = __expf(S[nt][3] - mc1);
            sum0 += S[nt][0] + S[nt][1];
            sum1 += S[nt][2] + S[nt][3];
        }
        sum0 += __shfl_xor_sync(0xffffffffu, sum0, 1);
        sum0 += __shfl_xor_sync(0xffffffffu, sum0, 2);
        sum1 += __shfl_xor_sync(0xffffffffu, sum1, 1);
        sum1 += __shfl_xor_sync(0xffffffffu, sum1, 2);
        l0 = l0 * cr0 + sum0;
        l1 = l1 * cr1 + sum1;
        m0 = mn0; m1 = mn1;

        #pragma unroll
        for (int nd = 0; nd < 8; nd++) {
            O[nd][0] *= cr0; O[nd][1] *= cr0;
            O[nd][2] *= cr1; O[nd][3] *= cr1;
        }

        // ---- O += P V ----
        #pragma unroll
        for (int s2 = 0; s2 < 4; s2++) {
            uint32_t pah[4], pal[4];
            pah[0] = pack_hi_lo(S[2 * s2][0],     S[2 * s2][1],     pal[0]);
            pah[1] = pack_hi_lo(S[2 * s2][2],     S[2 * s2][3],     pal[1]);
            pah[2] = pack_hi_lo(S[2 * s2 + 1][0], S[2 * s2 + 1][1], pal[2]);
            pah[3] = pack_hi_lo(S[2 * s2 + 1][2], S[2 * s2 + 1][3], pal[3]);

            uint32_t vbh[4][4], vbl[4][4];
            #pragma unroll
            for (int j = 0; j < 4; j++) {
                uint32_t off = (uint32_t)((j * 16 + bRow) * SRB + bKb + s2 * 32);
                ldsm_x4(vbh[j], sVh + off);
                ldsm_x4(vbl[j], sVl + off);
            }
            #pragma unroll
            for (int nd = 0; nd < 8; nd++) {
                const uint32_t* Bh = &vbh[nd >> 1][(nd & 1) * 2];
                const uint32_t* Bl = &vbl[nd >> 1][(nd & 1) * 2];
                MMA_BF16(O[nd], pal, Bh[0], Bh[1]);
                MMA_BF16(O[nd], pah, Bl[0], Bl[1]);
                MMA_BF16(O[nd], pah, Bh[0], Bh[1]);
            }
        }
        __syncthreads();
    }

    // ---- epilogue: O/l -> bf16 hi/lo planes ----
    const float inv0 = 1.0f / l0, inv1 = 1.0f / l1;
    const int r0 = i0, r1 = i0 + 8;
    #pragma unroll
    for (int nd = 0; nd < 8; nd++) {
        const int col = h * HDD + nd * 8 + 2 * t;
        uint32_t lo0, lo1;
        uint32_t hi0 = pack_hi_lo(O[nd][0] * inv0, O[nd][1] * inv0, lo0);
        uint32_t hi1 = pack_hi_lo(O[nd][2] * inv1, O[nd][3] * inv1, lo1);
        *(uint32_t*)(Oh + (size_t)(n * TT + r0) * DD + col) = hi0;
        *(uint32_t*)(Ol + (size_t)(n * TT + r0) * DD + col) = lo0;
        *(uint32_t*)(Oh + (size_t)(n * TT + r1) * DD + col) = hi1;
        *(uint32_t*)(Ol + (size_t)(n * TT + r1) * DD + col) = lo1;
    }
}

// ---------------------------------------------------------------------------
extern "C" void kernel_launch(void* const* d_in, const int* in_sizes, int n_in,
                              void* d_out, int out_size)
{
    const float* x     = (const float*)d_in[0];
    const float* w_qkv = (const float*)d_in[1];
    const float* w_out = (const float*)d_in[2];
    const float* b_out = (const float*)d_in[3];
    float* out = (float*)d_out;

    float* qkv = nullptr;
    uint16_t *ahi, *alo, *bhi, *blo, *qh, *ql, *kh, *kl, *vth, *vtl;
    cudaGetSymbolAddress((void**)&qkv, g_qkv);
    cudaGetSymbolAddress((void**)&ahi, g_ahi);
    cudaGetSymbolAddress((void**)&alo, g_alo);
    cudaGetSymbolAddress((void**)&bhi, g_bhi);
    cudaGetSymbolAddress((void**)&blo, g_blo);
    cudaGetSymbolAddress((void**)&qh,  g_qh);
    cudaGetSymbolAddress((void**)&ql,  g_ql);
    cudaGetSymbolAddress((void**)&kh,  g_kh);
    cudaGetSymbolAddress((void**)&kl,  g_kl);
    cudaGetSymbolAddress((void**)&vth, g_vth);
    cudaGetSymbolAddress((void**)&vtl, g_vtl);

    const int M = NB * TT;                 // 4096
    const int SMEM_GEMM = 2 * BUFB;        // 147456

    cudaFuncSetAttribute(gemm_3xbf16, cudaFuncAttributeMaxDynamicSharedMemorySize,
                         SMEM_GEMM);

    // split x and w_qkv
    {
        int n4 = M * DD / 4;
        split_kernel<<<(n4 + 255) / 256, 256>>>(x, ahi, alo, n4);
        n4 = 3 * DD * DD / 4;
        split_kernel<<<(n4 + 255) / 256, 256>>>(w_qkv, bhi, blo, n4);
    }
    // 1) qkv = x @ w_qkv^T
    {
        dim3 grid(3 * DD / 128, M / 128);
        gemm_3xbf16<<<grid, 256, SMEM_GEMM>>>(ahi, alo, bhi, blo, nullptr, qkv,
                                              M, 3 * DD, DD);
    }
    // 2) RoPE + split Q,K ; transpose + split V
    {
        int total = NB * TT * 2 * HH * 32;
        rope_split<<<total / 256, 256>>>(qkv, qh, ql, kh, kl);
        dim3 grid(TT / 64, HH, NB);
        vtrans_split<<<grid, 256>>>(qkv, vth, vtl);
    }
    // 3) flash attention -> writes A planes for GEMM2
    {
        dim3 grid(TT / 64, HH, NB);
        attn_mma<<<grid, 128>>>(qh, ql, kh, kl, vth, vtl, ahi, alo);
    }
    // split w_out
    {
        int n4 = DD * DD / 4;
        split_kernel<<<(n4 + 255) / 256, 256>>>(w_out, bhi, blo, n4);
    }
    // 4) out = attn @ w_out^T + b_out
    {
        dim3 grid(DD / 128, M / 128);
        gemm_3xbf16<<<grid, 256, SMEM_GEMM>>>(ahi, alo, bhi, blo, b_out, out,
                                              M, DD, DD);
    }
}

// round 11
// speedup vs baseline: 3.0285x; 1.0194x over previous
#include <cuda_runtime.h>
#include <cuda_bf16.h>
#include <math.h>
#include <stdint.h>

#define NB   2
#define TT   2048
#define DD   1024
#define HH   16
#define HDD  64
#define WL   127
#define WR   128

#define SRB  144   // attn smem row stride (bytes)
#define APLB 9216  // attn plane bytes: 64 rows * SRB

// GEMM staging (BK=32): 64B data + 16B pad per row
#define GSRB 80
#define GPLB (128 * GSRB)    // 10240
#define GBUF (4 * GPLB)      // 40960 bytes per stage (4 planes)

// Scratch (allocation-free)
__device__ float    g_qkv[(size_t)NB * TT * 3 * DD];
__device__ uint16_t g_ahi[(size_t)NB * TT * DD];
__device__ uint16_t g_alo[(size_t)NB * TT * DD];
__device__ uint16_t g_bhi[(size_t)3 * DD * DD];
__device__ uint16_t g_blo[(size_t)3 * DD * DD];
#define APL ((size_t)NB * HH * TT * HDD)
__device__ uint16_t g_qh[APL], g_ql[APL];
__device__ uint16_t g_kh[APL], g_kl[APL];
__device__ uint16_t g_vth[APL], g_vtl[APL];

// ---------------------------------------------------------------------------
__device__ __forceinline__ uint32_t smem_u32(const void* p) {
    uint32_t r;
    asm("{ .reg .u64 t; cvta.to.shared.u64 t, %1; cvt.u32.u64 %0, t; }"
        : "=r"(r) : "l"(p));
    return r;
}
__device__ __forceinline__ void cp_async16(uint32_t s, const void* g) {
    asm volatile("cp.async.cg.shared.global [%0], [%1], 16;" :: "r"(s), "l"(g));
}
__device__ __forceinline__ void cp_commit() {
    asm volatile("cp.async.commit_group;" ::: "memory");
}
template <int N_> __device__ __forceinline__ void cp_wait() {
    asm volatile("cp.async.wait_group %0;" :: "n"(N_) : "memory");
}
__device__ __forceinline__ void ldsm_x4(uint32_t* r, uint32_t addr) {
    asm volatile("ldmatrix.sync.aligned.m8n8.x4.shared.b16 {%0,%1,%2,%3}, [%4];"
                 : "=r"(r[0]), "=r"(r[1]), "=r"(r[2]), "=r"(r[3]) : "r"(addr));
}
__device__ __forceinline__ uint16_t f2bf(float x) {
    return __bfloat16_as_ushort(__float2bfloat16_rn(x));
}
__device__ __forceinline__ uint32_t pack_hi_lo(float a, float b, uint32_t& lo) {
    uint16_t ha = f2bf(a), hb = f2bf(b);
    float ra = a - __uint_as_float((uint32_t)ha << 16);
    float rb = b - __uint_as_float((uint32_t)hb << 16);
    lo = (uint32_t)f2bf(ra) | ((uint32_t)f2bf(rb) << 16);
    return (uint32_t)ha | ((uint32_t)hb << 16);
}

#define MMA_BF16(ACC, A, B0, B1)                                               \
    asm volatile(                                                              \
        "mma.sync.aligned.m16n8k16.row.col.f32.bf16.bf16.f32 "                 \
        "{%0,%1,%2,%3}, {%4,%5,%6,%7}, {%8,%9}, {%0,%1,%2,%3};"                \
        : "+f"(ACC[0]), "+f"(ACC[1]), "+f"(ACC[2]), "+f"(ACC[3])               \
        : "r"((A)[0]), "r"((A)[1]), "r"((A)[2]), "r"((A)[3]), "r"(B0), "r"(B1))

// ---------------------------------------------------------------------------
__global__ __launch_bounds__(256) void split_kernel(
    const float* __restrict__ in, uint16_t* __restrict__ hi,
    uint16_t* __restrict__ lo, int n4)
{
    int i = blockIdx.x * blockDim.x + threadIdx.x;
    if (i >= n4) return;
    float4 v = ((const float4*)in)[i];
    ushort4 h, l;
    h.x = f2bf(v.x); l.x = f2bf(v.x - __uint_as_float((uint32_t)h.x << 16));
    h.y = f2bf(v.y); l.y = f2bf(v.y - __uint_as_float((uint32_t)h.y << 16));
    h.z = f2bf(v.z); l.z = f2bf(v.z - __uint_as_float((uint32_t)h.z << 16));
    h.w = f2bf(v.w); l.w = f2bf(v.w - __uint_as_float((uint32_t)h.w << 16));
    ((ushort4*)hi)[i] = h;
    ((ushort4*)lo)[i] = l;
}

// ---------------------------------------------------------------------------
// 3-term bf16 mma GEMM, BK=32, 2 CTAs/SM target.
// ---------------------------------------------------------------------------
__global__ __launch_bounds__(256, 2) void gemm_3xbf16(
    const uint16_t* __restrict__ Ahi, const uint16_t* __restrict__ Alo,
    const uint16_t* __restrict__ Bhi, const uint16_t* __restrict__ Blo,
    const float* __restrict__ bias, float* __restrict__ C,
    int M, int N, int K)
{
    extern __shared__ char smem[];            // 2 stages x GBUF
    const int tid  = threadIdx.x;
    const int wid  = tid >> 5;
    const int lane = tid & 31;
    const int g    = lane >> 2;
    const int t    = lane & 3;
    const int warpM = (wid >> 2) * 64;
    const int warpN = (wid & 3) * 32;
    const int m0 = blockIdx.y * 128;
    const int n0 = blockIdx.x * 128;

    const uint32_t sbase = smem_u32(smem);

    const int aRow = ((lane >> 3) & 1) * 8 + (lane & 7);
    const int aKb  = (lane >> 4) * 16;
    const int bRow = ((lane >> 4) & 1) * 8 + (lane & 7);
    const int bKb  = ((lane >> 3) & 1) * 16;

    uint32_t aOffH[4], aOffL[4], bOffH[2], bOffL[2];
    #pragma unroll
    for (int mi = 0; mi < 4; mi++) {
        uint32_t off = (uint32_t)((warpM + mi * 16 + aRow) * GSRB + aKb);
        aOffH[mi] = sbase + off;
        aOffL[mi] = sbase + GPLB + off;
    }
    #pragma unroll
    for (int j = 0; j < 2; j++) {
        uint32_t off = (uint32_t)((warpN + j * 16 + bRow) * GSRB + bKb);
        bOffH[j] = sbase + 2u * GPLB + off;
        bOffL[j] = sbase + 3u * GPLB + off;
    }

    // stage one BK=32 tile (4 planes) into stage buffer b
    auto load_tile = [&](int kt, int b) {
        const uint32_t dst = sbase + (uint32_t)b * GBUF;
        const uint16_t* gp[4];
        gp[0] = Ahi + (size_t)m0 * K + kt * 32;
        gp[1] = Alo + (size_t)m0 * K + kt * 32;
        gp[2] = Bhi + (size_t)n0 * K + kt * 32;
        gp[3] = Blo + (size_t)n0 * K + kt * 32;
        #pragma unroll
        for (int c = 0; c < 2; c++) {
            int idx = tid + c * 256;          // 0..511
            int row = idx >> 2, j = idx & 3;  // 4 x 16B chunks per 64B row
            uint32_t soff = (uint32_t)(row * GSRB + j * 16);
            #pragma unroll
            for (int pl = 0; pl < 4; pl++)
                cp_async16(dst + pl * (uint32_t)GPLB + soff,
                           gp[pl] + (size_t)row * K + j * 8);
        }
        cp_commit();
    };

    float acc[4][4][4];
    #pragma unroll
    for (int mi = 0; mi < 4; mi++)
        #pragma unroll
        for (int ni = 0; ni < 4; ni++)
            #pragma unroll
            for (int r = 0; r < 4; r++) acc[mi][ni][r] = 0.0f;

    const int ktiles = K / 32;
    load_tile(0, 0);

    for (int kt = 0; kt < ktiles; kt++) {
        const int buf = kt & 1;
        if (kt + 1 < ktiles) { load_tile(kt + 1, buf ^ 1); cp_wait<1>(); }
        else                 { cp_wait<0>(); }
        __syncthreads();

        const uint32_t bo = (uint32_t)buf * GBUF;

        #pragma unroll
        for (int s = 0; s < 2; s++) {         // 2 k16-steps in BK=32
            const uint32_t so = bo + (uint32_t)s * 32u;
            uint32_t ah[4][4], al[4][4], bfh[2][4], bfl[2][4];
            #pragma unroll
            for (int mi = 0; mi < 4; mi++) ldsm_x4(ah[mi], aOffH[mi] + so);
            #pragma unroll
            for (int mi = 0; mi < 4; mi++) ldsm_x4(al[mi], aOffL[mi] + so);
            #pragma unroll
            for (int j = 0; j < 2; j++) ldsm_x4(bfh[j], bOffH[j] + so);
            #pragma unroll
            for (int j = 0; j < 2; j++) ldsm_x4(bfl[j], bOffL[j] + so);

            #pragma unroll
            for (int mi = 0; mi < 4; mi++)
                #pragma unroll
                for (int ni = 0; ni < 4; ni++) {
                    const uint32_t* Bh = &bfh[ni >> 1][(ni & 1) * 2];
                    const uint32_t* Bl = &bfl[ni >> 1][(ni & 1) * 2];
                    MMA_BF16(acc[mi][ni], al[mi], Bh[0], Bh[1]);
                    MMA_BF16(acc[mi][ni], ah[mi], Bl[0], Bl[1]);
                    MMA_BF16(acc[mi][ni], ah[mi], Bh[0], Bh[1]);
                }
        }
        __syncthreads();
    }

    #pragma unroll
    for (int mi = 0; mi < 4; mi++) {
        const int row = m0 + warpM + mi * 16 + g;
        #pragma unroll
        for (int ni = 0; ni < 4; ni++) {
            const int col = n0 + warpN + ni * 8 + t * 2;
            float bx = 0.f, by = 0.f;
            if (bias) { bx = bias[col]; by = bias[col + 1]; }
            float2 v0 = make_float2(acc[mi][ni][0] + bx, acc[mi][ni][1] + by);
            float2 v1 = make_float2(acc[mi][ni][2] + bx, acc[mi][ni][3] + by);
            *(float2*)(C + (size_t)row * N + col)       = v0;
            *(float2*)(C + (size_t)(row + 8) * N + col) = v1;
        }
    }
}

// ---------------------------------------------------------------------------
// RoPE + bf16 hi/lo split of q (scaled by 1/8) and k into [n,h,t,64] planes.
// ---------------------------------------------------------------------------
__global__ __launch_bounds__(256) void rope_split(
    const float* __restrict__ qkv,
    uint16_t* __restrict__ qh, uint16_t* __restrict__ ql,
    uint16_t* __restrict__ kh, uint16_t* __restrict__ kl)
{
    int idx = blockIdx.x * blockDim.x + threadIdx.x;
    int d  = idx & 31;
    int h  = (idx >> 5) & 15;
    int p  = (idx >> 9) & 1;
    int nt = idx >> 10;
    int t  = nt & (TT - 1);
    int n  = nt >> 11;

    float inv = exp2f(-0.41524101186092029f * (float)d);
    float fr  = (float)t * inv;
    float c, s;
    sincosf(fr, &s, &c);

    size_t base = ((size_t)nt * 3 + p) * DD + h * HDD + d;
    float x1 = qkv[base];
    float x2 = qkv[base + 32];
    float y1 = x1 * c - x2 * s;
    float y2 = x2 * c + x1 * s;
    if (p == 0) { y1 *= 0.125f; y2 *= 0.125f; }

    uint16_t* H = p ? kh : qh;
    uint16_t* L = p ? kl : ql;
    size_t dst = ((size_t)((n * HH + h) * TT) + t) * HDD + d;
    uint16_t h1 = f2bf(y1);
    uint16_t h2 = f2bf(y2);
    H[dst]      = h1;
    H[dst + 32] = h2;
    L[dst]      = f2bf(y1 - __uint_as_float((uint32_t)h1 << 16));
    L[dst + 32] = f2bf(y2 - __uint_as_float((uint32_t)h2 << 16));
}

// ---------------------------------------------------------------------------
// V transpose + split: qkv v part -> planes [n,h,d,t] hi/lo.
// ---------------------------------------------------------------------------
__global__ __launch_bounds__(256) void vtrans_split(
    const float* __restrict__ qkv,
    uint16_t* __restrict__ vh, uint16_t* __restrict__ vl)
{
    __shared__ float vs[64 * 65];
    const int t0 = blockIdx.x * 64;
    const int h  = blockIdx.y;
    const int n  = blockIdx.z;
    const int tid = threadIdx.x;

    for (int e = tid; e < 4096; e += 256) {
        int tr = e >> 6, d = e & 63;
        float v = qkv[(((size_t)(n * TT + t0 + tr) * 3) + 2) * DD + h * HDD + d];
        vs[d * 65 + tr] = v;
    }
    __syncthreads();
    for (int e = tid; e < 4096; e += 256) {
        int d = e >> 6, tc = e & 63;
        float v = vs[d * 65 + tc];
        uint16_t hb = f2bf(v);
        size_t dst = ((size_t)((n * HH + h) * HDD) + d) * TT + t0 + tc;
        vh[dst] = hb;
        vl[dst] = f2bf(v - __uint_as_float((uint32_t)hb << 16));
    }
}

// ---------------------------------------------------------------------------
// Flash attention, 3-term bf16 mma (unchanged from R10).
// ---------------------------------------------------------------------------
__global__ __launch_bounds__(128) void attn_mma(
    const uint16_t* __restrict__ Qh, const uint16_t* __restrict__ Ql,
    const uint16_t* __restrict__ Kh, const uint16_t* __restrict__ Kl,
    const uint16_t* __restrict__ Vh, const uint16_t* __restrict__ Vl,
    uint16_t* __restrict__ Oh, uint16_t* __restrict__ Ol)
{
    __shared__ char smem[4 * APLB];
    const uint32_t sb = smem_u32(smem);
    const uint32_t sKh = sb, sKl = sb + APLB, sVh = sb + 2 * APLB, sVl = sb + 3 * APLB;

    const int q0 = blockIdx.x * 64;
    const int h  = blockIdx.y;
    const int n  = blockIdx.z;
    const int tid = threadIdx.x;
    const int wid = tid >> 5;
    const int lane = tid & 31;
    const int g = lane >> 2;
    const int t = lane & 3;

    const size_t headoff  = (size_t)(n * HH + h) * TT * HDD;
    const size_t vheadoff = (size_t)(n * HH + h) * HDD * TT;

    const int aRow = ((lane >> 3) & 1) * 8 + (lane & 7);
    const int aKb  = (lane >> 4) * 16;
    const int bRow = ((lane >> 4) & 1) * 8 + (lane & 7);
    const int bKb  = ((lane >> 3) & 1) * 16;

    {
        #pragma unroll
        for (int c = 0; c < 4; c++) {
            int idx = tid + c * 128;
            int row = idx >> 3, j = idx & 7;
            uint32_t soff = (uint32_t)(row * SRB + j * 16);
            cp_async16(sKh + soff, Qh + headoff + (size_t)(q0 + row) * HDD + j * 8);
            cp_async16(sKl + soff, Ql + headoff + (size_t)(q0 + row) * HDD + j * 8);
        }
        cp_commit(); cp_wait<0>();
        __syncthreads();
    }
    uint32_t qfh[4][4], qfl[4][4];
    #pragma unroll
    for (int s = 0; s < 4; s++) {
        uint32_t off = (uint32_t)((wid * 16 + aRow) * SRB + aKb + s * 32);
        ldsm_x4(qfh[s], sKh + off);
        ldsm_x4(qfl[s], sKl + off);
    }
    __syncthreads();

    float O[8][4];
    #pragma unroll
    for (int nd = 0; nd < 8; nd++)
        #pragma unroll
        for (int c = 0; c < 4; c++) O[nd][c] = 0.0f;
    float m0 = -1e30f, m1 = -1e30f, l0 = 0.0f, l1 = 0.0f;

    const int klo = max(0, q0 - WL);
    const int khi = min(TT - 1, q0 + 63 + WR);
    const int i0  = q0 + wid * 16 + g;

    for (int kt = klo & ~63; kt <= khi; kt += 64) {
        #pragma unroll
        for (int c = 0; c < 4; c++) {
            int idx = tid + c * 128;
            int row = idx >> 3, j = idx & 7;
            uint32_t soff = (uint32_t)(row * SRB + j * 16);
            cp_async16(sKh + soff, Kh + headoff + (size_t)(kt + row) * HDD + j * 8);
            cp_async16(sKl + soff, Kl + headoff + (size_t)(kt + row) * HDD + j * 8);
            cp_async16(sVh + soff, Vh + vheadoff + (size_t)row * TT + kt + j * 8);
            cp_async16(sVl + soff, Vl + vheadoff + (size_t)row * TT + kt + j * 8);
        }
        cp_commit(); cp_wait<0>();
        __syncthreads();

        float S[8][4];
        #pragma unroll
        for (int nt = 0; nt < 8; nt++)
            #pragma unroll
            for (int c = 0; c < 4; c++) S[nt][c] = 0.0f;

        #pragma unroll
        for (int s = 0; s < 4; s++) {
            uint32_t kbh[4][4], kbl[4][4];
            #pragma unroll
            for (int j = 0; j < 4; j++) {
                uint32_t off = (uint32_t)((j * 16 + bRow) * SRB + bKb + s * 32);
                ldsm_x4(kbh[j], sKh + off);
                ldsm_x4(kbl[j], sKl + off);
            }
            #pragma unroll
            for (int nt = 0; nt < 8; nt++) {
                const uint32_t* Bh = &kbh[nt >> 1][(nt & 1) * 2];
                const uint32_t* Bl = &kbl[nt >> 1][(nt & 1) * 2];
                MMA_BF16(S[nt], qfl[s], Bh[0], Bh[1]);
                MMA_BF16(S[nt], qfh[s], Bl[0], Bl[1]);
                MMA_BF16(S[nt], qfh[s], Bh[0], Bh[1]);
            }
        }

        if (kt < q0 - 64 || kt > q0 + 64) {
            #pragma unroll
            for (int nt = 0; nt < 8; nt++)
                #pragma unroll
                for (int c = 0; c < 4; c++) {
                    int j = kt + nt * 8 + 2 * t + (c & 1);
                    int i = i0 + ((c >> 1) << 3);
                    if (j < i - WL || j > i + WR) S[nt][c] = -1e30f;
                }
        }

        float mx0 = -1e30f, mx1 = -1e30f;
        #pragma unroll
        for (int nt = 0; nt < 8; nt++) {
            mx0 = fmaxf(mx0, fmaxf(S[nt][0], S[nt][1]));
            mx1 = fmaxf(mx1, fmaxf(S[nt][2], S[nt][3]));
        }
        mx0 = fmaxf(mx0, __shfl_xor_sync(0xffffffffu, mx0, 1));
        mx0 = fmaxf(mx0, __shfl_xor_sync(0xffffffffu, mx0, 2));
        mx1 = fmaxf(mx1, __shfl_xor_sync(0xffffffffu, mx1, 1));
        mx1 = fmaxf(mx1, __shfl_xor_sync(0xffffffffu, mx1, 2));

        float mn0 = fmaxf(m0, mx0), mn1 = fmaxf(m1, mx1);
        float cr0 = __expf(m0 - mn0), cr1 = __expf(m1 - mn1);
        float mc0 = fmaxf(mn0, -1e29f), mc1 = fmaxf(mn1, -1e29f);

        float sum0 = 0.0f, sum1 = 0.0f;
        #pragma unroll
        for (int nt = 0; nt < 8; nt++) {
            S[nt][0] = __expf(S[nt][0] - mc0);
            S[nt][1] = __expf(S[nt][1] - mc0);
            S[nt][2] = __expf(S[nt][2] - mc1);
            S[nt][3] = __expf(S[nt][3] - mc1);
            sum0 += S[nt][0] + S[nt][1];
            sum1 += S[nt][2] + S[nt][3];
        }
        sum0 += __shfl_xor_sync(0xffffffffu, sum0, 1);
        sum0 += __shfl_xor_sync(0xffffffffu, sum0, 2);
        sum1 += __shfl_xor_sync(0xffffffffu, sum1, 1);
        sum1 += __shfl_xor_sync(0xffffffffu, sum1, 2);
        l0 = l0 * cr0 + sum0;
        l1 = l1 * cr1 + sum1;
        m0 = mn0; m1 = mn1;

        #pragma unroll
        for (int nd = 0; nd < 8; nd++) {
            O[nd][0] *= cr0; O[nd][1] *= cr0;
            O[nd][2] *= cr1; O[nd][3] *= cr1;
        }

        #pragma unroll
        for (int s2 = 0; s2 < 4; s2++) {
            uint32_t pah[4], pal[4];
            pah[0] = pack_hi_lo(S[2 * s2][0],     S[2 * s2][1],     pal[0]);
            pah[1] = pack_hi_lo(S[2 * s2][2],     S[2 * s2][3],     pal[1]);
            pah[2] = pack_hi_lo(S[2 * s2 + 1][0], S[2 * s2 + 1][1], pal[2]);
            pah[3] = pack_hi_lo(S[2 * s2 + 1][2], S[2 * s2 + 1][3], pal[3]);

            uint32_t vbh[4][4], vbl[4][4];
            #pragma unroll
            for (int j = 0; j < 4; j++) {
                uint32_t off = (uint32_t)((j * 16 + bRow) * SRB + bKb + s2 * 32);
                ldsm_x4(vbh[j], sVh + off);
                ldsm_x4(vbl[j], sVl + off);
            }
            #pragma unroll
            for (int nd = 0; nd < 8; nd++) {
                const uint32_t* Bh = &vbh[nd >> 1][(nd & 1) * 2];
                const uint32_t* Bl = &vbl[nd >> 1][(nd & 1) * 2];
                MMA_BF16(O[nd], pal, Bh[0], Bh[1]);
                MMA_BF16(O[nd], pah, Bl[0], Bl[1]);
                MMA_BF16(O[nd], pah, Bh[0], Bh[1]);
            }
        }
        __syncthreads();
    }

    const float inv0 = 1.0f / l0, inv1 = 1.0f / l1;
    const int r0 = i0, r1 = i0 + 8;
    #pragma unroll
    for (int nd = 0; nd < 8; nd++) {
        const int col = h * HDD + nd * 8 + 2 * t;
        uint32_t lo0, lo1;
        uint32_t hi0 = pack_hi_lo(O[nd][0] * inv0, O[nd][1] * inv0, lo0);
        uint32_t hi1 = pack_hi_lo(O[nd][2] * inv1, O[nd][3] * inv1, lo1);
        *(uint32_t*)(Oh + (size_t)(n * TT + r0) * DD + col) = hi0;
        *(uint32_t*)(Ol + (size_t)(n * TT + r0) * DD + col) = lo0;
        *(uint32_t*)(Oh + (size_t)(n * TT + r1) * DD + col) = hi1;
        *(uint32_t*)(Ol + (size_t)(n * TT + r1) * DD + col) = lo1;
    }
}

// ---------------------------------------------------------------------------
extern "C" void kernel_launch(void* const* d_in, const int* in_sizes, int n_in,
                              void* d_out, int out_size)
{
    const float* x     = (const float*)d_in[0];
    const float* w_qkv = (const float*)d_in[1];
    const float* w_out = (const float*)d_in[2];
    const float* b_out = (const float*)d_in[3];
    float* out = (float*)d_out;

    float* qkv = nullptr;
    uint16_t *ahi, *alo, *bhi, *blo, *qh, *ql, *kh, *kl, *vth, *vtl;
    cudaGetSymbolAddress((void**)&qkv, g_qkv);
    cudaGetSymbolAddress((void**)&ahi, g_ahi);
    cudaGetSymbolAddress((void**)&alo, g_alo);
    cudaGetSymbolAddress((void**)&bhi, g_bhi);
    cudaGetSymbolAddress((void**)&blo, g_blo);
    cudaGetSymbolAddress((void**)&qh,  g_qh);
    cudaGetSymbolAddress((void**)&ql,  g_ql);
    cudaGetSymbolAddress((void**)&kh,  g_kh);
    cudaGetSymbolAddress((void**)&kl,  g_kl);
    cudaGetSymbolAddress((void**)&vth, g_vth);
    cudaGetSymbolAddress((void**)&vtl, g_vtl);

    const int M = NB * TT;                 // 4096
    const int SMEM_GEMM = 2 * GBUF;        // 81920

    cudaFuncSetAttribute(gemm_3xbf16, cudaFuncAttributeMaxDynamicSharedMemorySize,
                         SMEM_GEMM);

    // split x and w_qkv
    {
        int n4 = M * DD / 4;
        split_kernel<<<(n4 + 255) / 256, 256>>>(x, ahi, alo, n4);
        n4 = 3 * DD * DD / 4;
        split_kernel<<<(n4 + 255) / 256, 256>>>(w_qkv, bhi, blo, n4);
    }
    // 1) qkv = x @ w_qkv^T
    {
        dim3 grid(3 * DD / 128, M / 128);
        gemm_3xbf16<<<grid, 256, SMEM_GEMM>>>(ahi, alo, bhi, blo, nullptr, qkv,
                                              M, 3 * DD, DD);
    }
    // 2) RoPE + split Q,K ; transpose + split V
    {
        int total = NB * TT * 2 * HH * 32;
        rope_split<<<total / 256, 256>>>(qkv, qh, ql, kh, kl);
        dim3 grid(TT / 64, HH, NB);
        vtrans_split<<<grid, 256>>>(qkv, vth, vtl);
    }
    // 3) flash attention -> writes A planes for GEMM2
    {
        dim3 grid(TT / 64, HH, NB);
        attn_mma<<<grid, 128>>>(qh, ql, kh, kl, vth, vtl, ahi, alo);
    }
    // split w_out
    {
        int n4 = DD * DD / 4;
        split_kernel<<<(n4 + 255) / 256, 256>>>(w_out, bhi, blo, n4);
    }
    // 4) out = attn @ w_out^T + b_out
    {
        dim3 grid(DD / 128, M / 128);
        gemm_3xbf16<<<grid, 256, SMEM_GEMM>>>(ahi, alo, bhi, blo, b_out, out,
                                              M, DD, DD);
    }
}